// round 7
// baseline (speedup 1.0000x reference)
#include <cuda_runtime.h>
#include <math.h>

#define N_NODES 50000
#define N_EDGES 800000
#define F_DIM   128
#define F4      32      // float4 per feature row
#define HID     256
#define NCLS    40

#define SCAN_BLOCKS ((N_NODES + 255) / 256)   // 196

// ---------------- device scratch (static: no allocation allowed) ----------------
// RULE (learned R3-R5): never pass __device__ symbol addresses from host code —
// on GB300 the host-side shadow resolves via ATS to HOST memory. All buffer
// selection happens inside device code.
__device__ int    g_deg[N_NODES];
__device__ int    g_rowstart[N_NODES + 1];
__device__ int    g_cursor[N_NODES];
__device__ int    g_bsum[SCAN_BLOCKS];
__device__ int    g_boff[SCAN_BLOCKS];
__device__ float  g_norm[N_NODES];
__device__ int2   g_csr[N_EDGES];           // (src, norm[src] as bits)
__device__ float4 g_x0[N_NODES * F4];
__device__ float4 g_x1[N_NODES * F4];
__device__ float4 g_y [N_NODES * F4];
__device__ float4 g_h [N_NODES * (HID / 4)];

// ---------------- build: degree ----------------
__global__ void zero_deg_kernel() {
    int i = blockIdx.x * blockDim.x + threadIdx.x;
    if (i < N_NODES) g_deg[i] = 0;
}

__global__ void deg_kernel(const int* __restrict__ dst) {
    int i = blockIdx.x * blockDim.x + threadIdx.x;
    if (i < N_EDGES) atomicAdd(&g_deg[dst[i]], 1);
}

// ---------------- hierarchical scan ----------------
__device__ __forceinline__ int warp_incl_scan(int v, int lane) {
#pragma unroll
    for (int o = 1; o < 32; o <<= 1) {
        int n = __shfl_up_sync(0xffffffffu, v, o);
        if (lane >= o) v += n;
    }
    return v;
}

__device__ __forceinline__ int block_incl_scan_256(int v, int tid) {
    __shared__ int ws[8];
    int lane = tid & 31, w = tid >> 5;
    int incl = warp_incl_scan(v, lane);
    if (lane == 31) ws[w] = incl;
    __syncthreads();
    if (w == 0) {
        int s = (lane < 8) ? ws[lane] : 0;
        s = warp_incl_scan(s, lane);
        if (lane < 8) ws[lane] = s;
    }
    __syncthreads();
    if (w > 0) incl += ws[w - 1];
    return incl;
}

// phase 1: block-local exclusive scan; also computes norm = rsqrt(max(deg,1))
__global__ void scan1_kernel() {
    int tid = threadIdx.x;
    int i = blockIdx.x * 256 + tid;
    int v = (i < N_NODES) ? g_deg[i] : 0;
    if (i < N_NODES) g_norm[i] = rsqrtf((float)(v < 1 ? 1 : v));
    int incl = block_incl_scan_256(v, tid);
    if (i < N_NODES) g_rowstart[i] = incl - v;
    if (tid == 255) g_bsum[blockIdx.x] = incl;
}

__global__ void scan2_kernel() {
    int tid = threadIdx.x;
    int v = (tid < SCAN_BLOCKS) ? g_bsum[tid] : 0;
    int incl = block_incl_scan_256(v, tid);
    if (tid < SCAN_BLOCKS) g_boff[tid] = incl - v;
}

__global__ void scan3_kernel() {
    int i = blockIdx.x * 256 + threadIdx.x;
    if (i < N_NODES) {
        int r = g_rowstart[i] + g_boff[blockIdx.x];
        g_rowstart[i] = r;
        g_cursor[i]   = r;
    }
    if (i == 0) g_rowstart[N_NODES] = N_EDGES;
}

// fill CSR: (src, norm[src]) interleaved
__global__ void fill_kernel(const int* __restrict__ src, const int* __restrict__ dst) {
    int i = blockIdx.x * blockDim.x + threadIdx.x;
    if (i < N_EDGES) {
        int s = src[i];
        int d = dst[i];
        int pos = atomicAdd(&g_cursor[d], 1);
        int2 v;
        v.x = s;
        v.y = __float_as_int(g_norm[s]);
        g_csr[pos] = v;
    }
}

// ---------------- init: stream features ONCE into device-resident x0 ----------
__global__ void init_kernel(const float4* __restrict__ feat) {
    int i = blockIdx.x * blockDim.x + threadIdx.x;
    if (i < N_NODES * F4) {
        g_x0[i] = feat[i];
    }
}

// ---------------- propagation: pull over CSR, fused y-accumulate ----------------
// block = 256 threads = 8 nodes x 32 lanes; lane owns 4 feature dims (float4)
// MODE 0 (first): y = x0[node] + acc          (init's y write fused away)
// MODE 1 (mid)  : y += acc
// MODE 2 (last) : y = (y + acc) * 0.25, NO xout write (x3 never needed)
template<int MODE>
__global__ void prop_kernel(int dir) {
    const float4* __restrict__ xin  = dir ? g_x1 : g_x0;
    float4*       __restrict__ xout = dir ? g_x0 : g_x1;

    int node = blockIdx.x * 8 + (threadIdx.x >> 5);
    int lane = threadIdx.x & 31;
    if (node >= N_NODES) return;

    int beg = g_rowstart[node];
    int end = g_rowstart[node + 1];

    float4 acc = make_float4(0.f, 0.f, 0.f, 0.f);
    int e = beg;
    for (; e + 4 <= end; e += 4) {
        int2 c0 = __ldg(&g_csr[e + 0]);
        int2 c1 = __ldg(&g_csr[e + 1]);
        int2 c2 = __ldg(&g_csr[e + 2]);
        int2 c3 = __ldg(&g_csr[e + 3]);
        float4 v0 = __ldg(&xin[c0.x * F4 + lane]);
        float4 v1 = __ldg(&xin[c1.x * F4 + lane]);
        float4 v2 = __ldg(&xin[c2.x * F4 + lane]);
        float4 v3 = __ldg(&xin[c3.x * F4 + lane]);
        float w0 = __int_as_float(c0.y);
        float w1 = __int_as_float(c1.y);
        float w2 = __int_as_float(c2.y);
        float w3 = __int_as_float(c3.y);
        acc.x = fmaf(v0.x, w0, acc.x); acc.y = fmaf(v0.y, w0, acc.y);
        acc.z = fmaf(v0.z, w0, acc.z); acc.w = fmaf(v0.w, w0, acc.w);
        acc.x = fmaf(v1.x, w1, acc.x); acc.y = fmaf(v1.y, w1, acc.y);
        acc.z = fmaf(v1.z, w1, acc.z); acc.w = fmaf(v1.w, w1, acc.w);
        acc.x = fmaf(v2.x, w2, acc.x); acc.y = fmaf(v2.y, w2, acc.y);
        acc.z = fmaf(v2.z, w2, acc.z); acc.w = fmaf(v2.w, w2, acc.w);
        acc.x = fmaf(v3.x, w3, acc.x); acc.y = fmaf(v3.y, w3, acc.y);
        acc.z = fmaf(v3.z, w3, acc.z); acc.w = fmaf(v3.w, w3, acc.w);
    }
    for (; e < end; e++) {
        int2 c = __ldg(&g_csr[e]);
        float w = __int_as_float(c.y);
        float4 v = __ldg(&xin[c.x * F4 + lane]);
        acc.x = fmaf(v.x, w, acc.x); acc.y = fmaf(v.y, w, acc.y);
        acc.z = fmaf(v.z, w, acc.z); acc.w = fmaf(v.w, w, acc.w);
    }

    float nd = g_norm[node];
    acc.x *= nd; acc.y *= nd; acc.z *= nd; acc.w *= nd;

    int idx = node * F4 + lane;
    if (MODE == 0) {
        xout[idx] = acc;
        float4 f = __ldg(&xin[idx]);          // features row (hot in L2)
        f.x += acc.x; f.y += acc.y; f.z += acc.z; f.w += acc.w;
        g_y[idx] = f;
    } else if (MODE == 1) {
        xout[idx] = acc;
        float4 yv = g_y[idx];
        yv.x += acc.x; yv.y += acc.y; yv.z += acc.z; yv.w += acc.w;
        g_y[idx] = yv;
    } else {
        float4 yv = g_y[idx];
        yv.x = (yv.x + acc.x) * 0.25f;
        yv.y = (yv.y + acc.y) * 0.25f;
        yv.z = (yv.z + acc.z) * 0.25f;
        yv.w = (yv.w + acc.w) * 0.25f;
        g_y[idx] = yv;                        // y now pre-scaled: feat = y
    }
}

// ---------------- GEMM1 (tensor cores): h = relu( y @ W1 + b1 ) -----------------
// tf32x3 precision trick: a = ah + al (tf32 each); D += al*bh + ah*bl + ah*bh
// BM=64, BN=128, BK=16, 256 threads = 8 warps (2m x 4n), warp tile 32x32
__device__ __forceinline__ float2 tf32_split(float a) {
    unsigned hi;
    asm("cvt.rna.tf32.f32 %0, %1;" : "=r"(hi) : "f"(a));
    float hf = __uint_as_float(hi);
    float lo = a - hf;
    unsigned lo32;
    asm("cvt.rna.tf32.f32 %0, %1;" : "=r"(lo32) : "f"(lo));
    return make_float2(hf, __uint_as_float(lo32));
}

#define MMA_TF32(D, A, B) \
    asm volatile("mma.sync.aligned.m16n8k8.row.col.f32.tf32.tf32.f32 " \
        "{%0,%1,%2,%3}, {%4,%5,%6,%7}, {%8,%9}, {%0,%1,%2,%3};" \
        : "+f"((D)[0]), "+f"((D)[1]), "+f"((D)[2]), "+f"((D)[3]) \
        : "r"((A)[0]), "r"((A)[1]), "r"((A)[2]), "r"((A)[3]), \
          "r"((B)[0]), "r"((B)[1]))

__global__ __launch_bounds__(256) void gemm1_kernel(const float* __restrict__ W1,
                                                    const float* __restrict__ b1) {
    __shared__ float2 As2[16][68];    // [k][m]  (hi, lo)
    __shared__ float2 Bs2[16][132];   // [k][n]  (hi, lo)

    int tid  = threadIdx.x;
    int lane = tid & 31;
    int wid  = tid >> 5;
    int warp_m = wid & 1;            // 0..1 -> 32 rows each
    int warp_n = wid >> 1;           // 0..3 -> 32 cols each
    int qrow = lane >> 2;            // 0..7
    int qcol = lane & 3;             // 0..3

    int m0 = blockIdx.x * 64;
    int n0 = blockIdx.y * 128;

    const float* y = (const float*)g_y;

    int arow = tid >> 2;             // 0..63
    int ak   = (tid & 3) * 4;        // 0,4,8,12
    int brow = tid >> 4;             // 0..15
    int bc   = (tid & 15) * 8;       // 0..120

    float d[2][4][4];
#pragma unroll
    for (int t = 0; t < 2; t++)
#pragma unroll
        for (int u = 0; u < 4; u++)
#pragma unroll
            for (int i = 0; i < 4; i++) d[t][u][i] = 0.f;

    for (int k0 = 0; k0 < F_DIM; k0 += 16) {
        // stage A (64 x 16), split to tf32 hi/lo
        {
            int gm = m0 + arow;
            float4 av = make_float4(0.f, 0.f, 0.f, 0.f);
            if (gm < N_NODES) av = *(const float4*)&y[gm * F_DIM + k0 + ak];
            As2[ak + 0][arow] = tf32_split(av.x);
            As2[ak + 1][arow] = tf32_split(av.y);
            As2[ak + 2][arow] = tf32_split(av.z);
            As2[ak + 3][arow] = tf32_split(av.w);
        }
        // stage B (16 x 128), split to tf32 hi/lo
        {
            const float* wrow = &W1[(k0 + brow) * HID + n0 + bc];
            float4 bv0 = *(const float4*)&wrow[0];
            float4 bv1 = *(const float4*)&wrow[4];
            Bs2[brow][bc + 0] = tf32_split(bv0.x);
            Bs2[brow][bc + 1] = tf32_split(bv0.y);
            Bs2[brow][bc + 2] = tf32_split(bv0.z);
            Bs2[brow][bc + 3] = tf32_split(bv0.w);
            Bs2[brow][bc + 4] = tf32_split(bv1.x);
            Bs2[brow][bc + 5] = tf32_split(bv1.y);
            Bs2[brow][bc + 6] = tf32_split(bv1.z);
            Bs2[brow][bc + 7] = tf32_split(bv1.w);
        }
        __syncthreads();

#pragma unroll
        for (int k8 = 0; k8 < 16; k8 += 8) {
            unsigned ah[2][4], al[2][4], bh[4][2], bl[4][2];
            int kA = k8 + qcol;
#pragma unroll
            for (int t = 0; t < 2; t++) {
                int mr = warp_m * 32 + t * 16 + qrow;
                float2 f0 = As2[kA][mr];
                float2 f1 = As2[kA][mr + 8];
                float2 f2 = As2[kA + 4][mr];
                float2 f3 = As2[kA + 4][mr + 8];
                ah[t][0] = __float_as_uint(f0.x); al[t][0] = __float_as_uint(f0.y);
                ah[t][1] = __float_as_uint(f1.x); al[t][1] = __float_as_uint(f1.y);
                ah[t][2] = __float_as_uint(f2.x); al[t][2] = __float_as_uint(f2.y);
                ah[t][3] = __float_as_uint(f3.x); al[t][3] = __float_as_uint(f3.y);
            }
#pragma unroll
            for (int u = 0; u < 4; u++) {
                int bcol = warp_n * 32 + u * 8 + qrow;
                float2 g0 = Bs2[kA][bcol];
                float2 g1 = Bs2[kA + 4][bcol];
                bh[u][0] = __float_as_uint(g0.x); bl[u][0] = __float_as_uint(g0.y);
                bh[u][1] = __float_as_uint(g1.x); bl[u][1] = __float_as_uint(g1.y);
            }
#pragma unroll
            for (int t = 0; t < 2; t++)
#pragma unroll
                for (int u = 0; u < 4; u++) {
                    MMA_TF32(d[t][u], al[t], bh[u]);
                    MMA_TF32(d[t][u], ah[t], bl[u]);
                    MMA_TF32(d[t][u], ah[t], bh[u]);
                }
        }
        __syncthreads();
    }

    // epilogue: bias + relu + store
    float* h = (float*)g_h;
#pragma unroll
    for (int t = 0; t < 2; t++) {
        int r0 = m0 + warp_m * 32 + t * 16 + qrow;
#pragma unroll
        for (int u = 0; u < 4; u++) {
            int c = n0 + warp_n * 32 + u * 8 + qcol * 2;
            float2 bb = *(const float2*)&b1[c];
            if (r0 < N_NODES) {
                float2 o;
                o.x = fmaxf(d[t][u][0] + bb.x, 0.f);
                o.y = fmaxf(d[t][u][1] + bb.y, 0.f);
                *(float2*)&h[r0 * HID + c] = o;
            }
            if (r0 + 8 < N_NODES) {
                float2 o;
                o.x = fmaxf(d[t][u][2] + bb.x, 0.f);
                o.y = fmaxf(d[t][u][3] + bb.y, 0.f);
                *(float2*)&h[(r0 + 8) * HID + c] = o;
            }
        }
    }
}

// ---------------- GEMM2 + log_softmax fused: out = logsoftmax(h @ W2 + b2) -------
__global__ void gemm2_kernel(const float* __restrict__ W2, const float* __restrict__ b2,
                             float* __restrict__ out) {
    __shared__ float w2c[32][44];
    __shared__ float hc[32][33];
    __shared__ float lg[32][41];
    __shared__ float rm[32], rs[32];

    int tid = threadIdx.x;          // 0..319
    int r = tid / 10;               // 0..31
    int g = tid % 10;               // 0..9  -> classes 4g..4g+3
    int m0 = blockIdx.x * 32;

    const float* h = (const float*)g_h;

    float a0 = 0.f, a1 = 0.f, a2 = 0.f, a3 = 0.f;

    for (int kb = 0; kb < HID; kb += 32) {
        for (int idx = tid; idx < 32 * 32; idx += 320) {
            int rr = idx >> 5, kk = idx & 31;
            int row = m0 + rr;
            hc[rr][kk] = (row < N_NODES) ? h[row * HID + kb + kk] : 0.f;
        }
        for (int idx = tid; idx < 32 * 40; idx += 320) {
            int kk = idx / 40, cc = idx % 40;
            w2c[kk][cc] = W2[(kb + kk) * NCLS + cc];
        }
        __syncthreads();
#pragma unroll
        for (int kk = 0; kk < 32; kk++) {
            float hv = hc[r][kk];
            float4 wv = *(const float4*)&w2c[kk][g * 4];
            a0 = fmaf(hv, wv.x, a0);
            a1 = fmaf(hv, wv.y, a1);
            a2 = fmaf(hv, wv.z, a2);
            a3 = fmaf(hv, wv.w, a3);
        }
        __syncthreads();
    }

    lg[r][g * 4 + 0] = a0 + b2[g * 4 + 0];
    lg[r][g * 4 + 1] = a1 + b2[g * 4 + 1];
    lg[r][g * 4 + 2] = a2 + b2[g * 4 + 2];
    lg[r][g * 4 + 3] = a3 + b2[g * 4 + 3];
    __syncthreads();

    if (tid < 32) {
        float m = -1e30f;
#pragma unroll
        for (int c = 0; c < NCLS; c++) m = fmaxf(m, lg[tid][c]);
        float s = 0.f;
#pragma unroll
        for (int c = 0; c < NCLS; c++) s += expf(lg[tid][c] - m);
        rm[tid] = m;
        rs[tid] = logf(s);
    }
    __syncthreads();

    int row = m0 + r;
    if (row < N_NODES) {
        float sub = rm[r] + rs[r];
        out[row * NCLS + g * 4 + 0] = lg[r][g * 4 + 0] - sub;
        out[row * NCLS + g * 4 + 1] = lg[r][g * 4 + 1] - sub;
        out[row * NCLS + g * 4 + 2] = lg[r][g * 4 + 2] - sub;
        out[row * NCLS + g * 4 + 3] = lg[r][g * 4 + 3] - sub;
    }
}

// ---------------- launch ----------------
extern "C" void kernel_launch(void* const* d_in, const int* in_sizes, int n_in,
                              void* d_out, int out_size) {
    const float* features = (const float*)d_in[0];
    const int*   src      = (const int*)d_in[1];
    const int*   dst      = (const int*)d_in[2];
    const float* W1       = (const float*)d_in[3];
    const float* b1       = (const float*)d_in[4];
    const float* W2       = (const float*)d_in[5];
    const float* b2       = (const float*)d_in[6];
    float*       out      = (float*)d_out;

    const int NB  = (N_NODES + 255) / 256;      // 196
    const int EB  = (N_EDGES + 255) / 256;      // 3125
    const int IB  = (N_NODES * F4 + 255) / 256; // 6250
    const int PB  = (N_NODES + 7) / 8;          // 6250

    zero_deg_kernel<<<NB, 256>>>();
    deg_kernel<<<EB, 256>>>(dst);
    scan1_kernel<<<SCAN_BLOCKS, 256>>>();
    scan2_kernel<<<1, 256>>>();
    scan3_kernel<<<SCAN_BLOCKS, 256>>>();
    fill_kernel<<<EB, 256>>>(src, dst);
    init_kernel<<<IB, 256>>>((const float4*)features);

    prop_kernel<0><<<PB, 256>>>(0);   // x0 -> x1, y = feat + x1
    prop_kernel<1><<<PB, 256>>>(1);   // x1 -> x0, y += x2
    prop_kernel<2><<<PB, 256>>>(0);   // x0 -> (x3), y = (y + x3)/4

    dim3 g1((N_NODES + 63) / 64, HID / 128);    // (782, 2)
    gemm1_kernel<<<g1, 256>>>(W1, b1);

    const int G2B = (N_NODES + 31) / 32;        // 1563
    gemm2_kernel<<<G2B, 320>>>(W2, b2, out);
}

// round 8
// speedup vs baseline: 1.0104x; 1.0104x over previous
#include <cuda_runtime.h>
#include <math.h>

#define N_NODES 50000
#define N_EDGES 800000
#define F_DIM   128
#define F4      32      // float4 per feature row
#define HID     256
#define NCLS    40

#define SCAN_BLOCKS ((N_NODES + 255) / 256)   // 196

// ---------------- device scratch (static: no allocation allowed) ----------------
// RULE (learned R3-R5): never pass __device__ symbol addresses from host code —
// on GB300 the host-side shadow resolves via ATS to HOST memory. All buffer
// selection happens inside device code.
__device__ int    g_deg[N_NODES];
__device__ int    g_rowstart[N_NODES + 1];
__device__ int    g_cursor[N_NODES];
__device__ int    g_bsum[SCAN_BLOCKS];
__device__ float  g_norm[N_NODES];
__device__ int2   g_csr[N_EDGES];           // (src, norm[src] as bits)
__device__ float4 g_x0[N_NODES * F4];
__device__ float4 g_x1[N_NODES * F4];
__device__ float4 g_y [N_NODES * F4];
__device__ float4 g_h [N_NODES * (HID / 4)];

// ---------------- build: degree ----------------
__global__ void zero_deg_kernel() {
    int i = blockIdx.x * blockDim.x + threadIdx.x;
    if (i < N_NODES) g_deg[i] = 0;
}

__global__ void deg_kernel(const int* __restrict__ dst) {
    int i = blockIdx.x * blockDim.x + threadIdx.x;
    if (i < N_EDGES) atomicAdd(&g_deg[dst[i]], 1);
}

// ---------------- hierarchical scan ----------------
__device__ __forceinline__ int warp_incl_scan(int v, int lane) {
#pragma unroll
    for (int o = 1; o < 32; o <<= 1) {
        int n = __shfl_up_sync(0xffffffffu, v, o);
        if (lane >= o) v += n;
    }
    return v;
}

__device__ __forceinline__ int block_incl_scan_256(int v, int tid) {
    __shared__ int ws[8];
    int lane = tid & 31, w = tid >> 5;
    int incl = warp_incl_scan(v, lane);
    if (lane == 31) ws[w] = incl;
    __syncthreads();
    if (w == 0) {
        int s = (lane < 8) ? ws[lane] : 0;
        s = warp_incl_scan(s, lane);
        if (lane < 8) ws[lane] = s;
    }
    __syncthreads();
    if (w > 0) incl += ws[w - 1];
    return incl;
}

// phase 1: block-local exclusive scan; also computes norm = rsqrt(max(deg,1))
__global__ void scan1_kernel() {
    int tid = threadIdx.x;
    int i = blockIdx.x * 256 + tid;
    int v = (i < N_NODES) ? g_deg[i] : 0;
    if (i < N_NODES) g_norm[i] = rsqrtf((float)(v < 1 ? 1 : v));
    int incl = block_incl_scan_256(v, tid);
    if (i < N_NODES) g_rowstart[i] = incl - v;
    if (tid == 255) g_bsum[blockIdx.x] = incl;
}

// phase 2 (merged): each block reduces its own bsum prefix, adds offsets
__global__ void scan3_kernel() {
    __shared__ int ssum[8];
    int tid = threadIdx.x;
    int bid = blockIdx.x;
    int lane = tid & 31, w = tid >> 5;

    int v = (tid < bid && tid < SCAN_BLOCKS) ? g_bsum[tid] : 0;
#pragma unroll
    for (int o = 16; o > 0; o >>= 1) v += __shfl_down_sync(0xffffffffu, v, o);
    if (lane == 0) ssum[w] = v;
    __syncthreads();
    if (tid == 0) {
        int s = 0;
#pragma unroll
        for (int i = 0; i < 8; i++) s += ssum[i];
        ssum[0] = s;
    }
    __syncthreads();
    int off = ssum[0];

    int i = bid * 256 + tid;
    if (i < N_NODES) {
        int r = g_rowstart[i] + off;
        g_rowstart[i] = r;
        g_cursor[i]   = r;
    }
    if (i == 0) g_rowstart[N_NODES] = N_EDGES;
}

// fill CSR: (src, norm[src]) interleaved
__global__ void fill_kernel(const int* __restrict__ src, const int* __restrict__ dst) {
    int i = blockIdx.x * blockDim.x + threadIdx.x;
    if (i < N_EDGES) {
        int s = src[i];
        int d = dst[i];
        int pos = atomicAdd(&g_cursor[d], 1);
        int2 v;
        v.x = s;
        v.y = __float_as_int(g_norm[s]);
        g_csr[pos] = v;
    }
}

// ---------------- init: stream features ONCE into device-resident x0 ----------
__global__ void init_kernel(const float4* __restrict__ feat) {
    int i = blockIdx.x * blockDim.x + threadIdx.x;
    if (i < N_NODES * F4) {
        g_x0[i] = feat[i];
    }
}

// ---------------- propagation: pull over CSR, fused y-accumulate ----------------
// block = 256 threads = 8 nodes x 32 lanes; lane owns 4 feature dims (float4)
// MODE 0 (first): y = x0[node] + acc
// MODE 1 (mid)  : y += acc
// MODE 2 (last) : y = (y + acc) * 0.25, NO xout write (x3 never needed)
template<int MODE>
__global__ void prop_kernel(int dir) {
    const float4* __restrict__ xin  = dir ? g_x1 : g_x0;
    float4*       __restrict__ xout = dir ? g_x0 : g_x1;

    int node = blockIdx.x * 8 + (threadIdx.x >> 5);
    int lane = threadIdx.x & 31;
    if (node >= N_NODES) return;

    int beg = g_rowstart[node];
    int end = g_rowstart[node + 1];

    float4 acc = make_float4(0.f, 0.f, 0.f, 0.f);
    int e = beg;
    for (; e + 4 <= end; e += 4) {
        int2 c0 = __ldg(&g_csr[e + 0]);
        int2 c1 = __ldg(&g_csr[e + 1]);
        int2 c2 = __ldg(&g_csr[e + 2]);
        int2 c3 = __ldg(&g_csr[e + 3]);
        float4 v0 = __ldg(&xin[c0.x * F4 + lane]);
        float4 v1 = __ldg(&xin[c1.x * F4 + lane]);
        float4 v2 = __ldg(&xin[c2.x * F4 + lane]);
        float4 v3 = __ldg(&xin[c3.x * F4 + lane]);
        float w0 = __int_as_float(c0.y);
        float w1 = __int_as_float(c1.y);
        float w2 = __int_as_float(c2.y);
        float w3 = __int_as_float(c3.y);
        acc.x = fmaf(v0.x, w0, acc.x); acc.y = fmaf(v0.y, w0, acc.y);
        acc.z = fmaf(v0.z, w0, acc.z); acc.w = fmaf(v0.w, w0, acc.w);
        acc.x = fmaf(v1.x, w1, acc.x); acc.y = fmaf(v1.y, w1, acc.y);
        acc.z = fmaf(v1.z, w1, acc.z); acc.w = fmaf(v1.w, w1, acc.w);
        acc.x = fmaf(v2.x, w2, acc.x); acc.y = fmaf(v2.y, w2, acc.y);
        acc.z = fmaf(v2.z, w2, acc.z); acc.w = fmaf(v2.w, w2, acc.w);
        acc.x = fmaf(v3.x, w3, acc.x); acc.y = fmaf(v3.y, w3, acc.y);
        acc.z = fmaf(v3.z, w3, acc.z); acc.w = fmaf(v3.w, w3, acc.w);
    }
    for (; e < end; e++) {
        int2 c = __ldg(&g_csr[e]);
        float w = __int_as_float(c.y);
        float4 v = __ldg(&xin[c.x * F4 + lane]);
        acc.x = fmaf(v.x, w, acc.x); acc.y = fmaf(v.y, w, acc.y);
        acc.z = fmaf(v.z, w, acc.z); acc.w = fmaf(v.w, w, acc.w);
    }

    float nd = g_norm[node];
    acc.x *= nd; acc.y *= nd; acc.z *= nd; acc.w *= nd;

    int idx = node * F4 + lane;
    if (MODE == 0) {
        xout[idx] = acc;
        float4 f = __ldg(&xin[idx]);          // features row (hot in L2)
        f.x += acc.x; f.y += acc.y; f.z += acc.z; f.w += acc.w;
        g_y[idx] = f;
    } else if (MODE == 1) {
        xout[idx] = acc;
        float4 yv = g_y[idx];
        yv.x += acc.x; yv.y += acc.y; yv.z += acc.z; yv.w += acc.w;
        g_y[idx] = yv;
    } else {
        float4 yv = g_y[idx];
        yv.x = (yv.x + acc.x) * 0.25f;
        yv.y = (yv.y + acc.y) * 0.25f;
        yv.z = (yv.z + acc.z) * 0.25f;
        yv.w = (yv.w + acc.w) * 0.25f;
        g_y[idx] = yv;                        // y now pre-scaled: feat = y
    }
}

// ---------------- GEMM1: h = relu( y @ W1 + b1 )  [50000,128]x[128,256] --------
// BM=128, BN=128, BK=16, 256 threads, 8x8 per thread (scalar FFMA, 94% FMA mix)
__global__ __launch_bounds__(256, 2) void gemm1_kernel(const float* __restrict__ W1,
                                                       const float* __restrict__ b1) {
    __shared__ float As[16][132];   // [k][m], padded
    __shared__ float Bs[16][128];   // [k][n]

    int tid = threadIdx.x;
    int m0 = blockIdx.x * 128;
    int n0 = blockIdx.y * 128;
    int ty = tid >> 4;          // 0..15 -> 8 rows each
    int tx = tid & 15;          // 0..15 -> 8 cols each

    const float* y = (const float*)g_y;

    int arow = tid >> 1;            // 0..127
    int ak   = (tid & 1) * 8;       // 0 or 8
    int brow = tid >> 4;            // 0..15
    int bc   = (tid & 15) * 8;      // 0..120

    float acc[8][8];
#pragma unroll
    for (int i = 0; i < 8; i++)
#pragma unroll
        for (int j = 0; j < 8; j++) acc[i][j] = 0.f;

    for (int k0 = 0; k0 < F_DIM; k0 += 16) {
        // stage A: 128 rows x 16 k, 2 float4 per thread
        {
            int gm = m0 + arow;
            float4 av0 = make_float4(0.f, 0.f, 0.f, 0.f);
            float4 av1 = make_float4(0.f, 0.f, 0.f, 0.f);
            if (gm < N_NODES) {
                av0 = *(const float4*)&y[gm * F_DIM + k0 + ak];
                av1 = *(const float4*)&y[gm * F_DIM + k0 + ak + 4];
            }
            As[ak + 0][arow] = av0.x;
            As[ak + 1][arow] = av0.y;
            As[ak + 2][arow] = av0.z;
            As[ak + 3][arow] = av0.w;
            As[ak + 4][arow] = av1.x;
            As[ak + 5][arow] = av1.y;
            As[ak + 6][arow] = av1.z;
            As[ak + 7][arow] = av1.w;
        }
        // stage B: 16 k x 128 n, 2 float4 per thread
        {
            const float* wrow = &W1[(k0 + brow) * HID + n0 + bc];
            *(float4*)&Bs[brow][bc]     = *(const float4*)&wrow[0];
            *(float4*)&Bs[brow][bc + 4] = *(const float4*)&wrow[4];
        }
        __syncthreads();
#pragma unroll
        for (int kk = 0; kk < 16; kk++) {
            float4 a0 = *(const float4*)&As[kk][ty * 8];
            float4 a1 = *(const float4*)&As[kk][ty * 8 + 4];
            float4 b0 = *(const float4*)&Bs[kk][tx * 8];
            float4 b1v = *(const float4*)&Bs[kk][tx * 8 + 4];
            float a_[8] = {a0.x, a0.y, a0.z, a0.w, a1.x, a1.y, a1.z, a1.w};
            float b_[8] = {b0.x, b0.y, b0.z, b0.w, b1v.x, b1v.y, b1v.z, b1v.w};
#pragma unroll
            for (int i = 0; i < 8; i++)
#pragma unroll
                for (int j = 0; j < 8; j++)
                    acc[i][j] = fmaf(a_[i], b_[j], acc[i][j]);
        }
        __syncthreads();
    }

    float4 bias0 = *(const float4*)&b1[n0 + tx * 8];
    float4 bias1 = *(const float4*)&b1[n0 + tx * 8 + 4];
    float* h = (float*)g_h;
#pragma unroll
    for (int i = 0; i < 8; i++) {
        int gm = m0 + ty * 8 + i;
        if (gm < N_NODES) {
            float4 o0, o1;
            o0.x = fmaxf(acc[i][0] + bias0.x, 0.f);
            o0.y = fmaxf(acc[i][1] + bias0.y, 0.f);
            o0.z = fmaxf(acc[i][2] + bias0.z, 0.f);
            o0.w = fmaxf(acc[i][3] + bias0.w, 0.f);
            o1.x = fmaxf(acc[i][4] + bias1.x, 0.f);
            o1.y = fmaxf(acc[i][5] + bias1.y, 0.f);
            o1.z = fmaxf(acc[i][6] + bias1.z, 0.f);
            o1.w = fmaxf(acc[i][7] + bias1.w, 0.f);
            *(float4*)&h[gm * HID + n0 + tx * 8]     = o0;
            *(float4*)&h[gm * HID + n0 + tx * 8 + 4] = o1;
        }
    }
}

// ---------------- GEMM2 + log_softmax fused: out = logsoftmax(h @ W2 + b2) -------
__global__ void gemm2_kernel(const float* __restrict__ W2, const float* __restrict__ b2,
                             float* __restrict__ out) {
    __shared__ float w2c[32][44];
    __shared__ float hc[32][33];
    __shared__ float lg[32][41];
    __shared__ float rm[32], rs[32];

    int tid = threadIdx.x;          // 0..319
    int r = tid / 10;               // 0..31
    int g = tid % 10;               // 0..9  -> classes 4g..4g+3
    int m0 = blockIdx.x * 32;

    const float* h = (const float*)g_h;

    float a0 = 0.f, a1 = 0.f, a2 = 0.f, a3 = 0.f;

    for (int kb = 0; kb < HID; kb += 32) {
        for (int idx = tid; idx < 32 * 32; idx += 320) {
            int rr = idx >> 5, kk = idx & 31;
            int row = m0 + rr;
            hc[rr][kk] = (row < N_NODES) ? h[row * HID + kb + kk] : 0.f;
        }
        for (int idx = tid; idx < 32 * 40; idx += 320) {
            int kk = idx / 40, cc = idx % 40;
            w2c[kk][cc] = W2[(kb + kk) * NCLS + cc];
        }
        __syncthreads();
#pragma unroll
        for (int kk = 0; kk < 32; kk++) {
            float hv = hc[r][kk];
            float4 wv = *(const float4*)&w2c[kk][g * 4];
            a0 = fmaf(hv, wv.x, a0);
            a1 = fmaf(hv, wv.y, a1);
            a2 = fmaf(hv, wv.z, a2);
            a3 = fmaf(hv, wv.w, a3);
        }
        __syncthreads();
    }

    lg[r][g * 4 + 0] = a0 + b2[g * 4 + 0];
    lg[r][g * 4 + 1] = a1 + b2[g * 4 + 1];
    lg[r][g * 4 + 2] = a2 + b2[g * 4 + 2];
    lg[r][g * 4 + 3] = a3 + b2[g * 4 + 3];
    __syncthreads();

    if (tid < 32) {
        float m = -1e30f;
#pragma unroll
        for (int c = 0; c < NCLS; c++) m = fmaxf(m, lg[tid][c]);
        float s = 0.f;
#pragma unroll
        for (int c = 0; c < NCLS; c++) s += expf(lg[tid][c] - m);
        rm[tid] = m;
        rs[tid] = logf(s);
    }
    __syncthreads();

    int row = m0 + r;
    if (row < N_NODES) {
        float sub = rm[r] + rs[r];
        out[row * NCLS + g * 4 + 0] = lg[r][g * 4 + 0] - sub;
        out[row * NCLS + g * 4 + 1] = lg[r][g * 4 + 1] - sub;
        out[row * NCLS + g * 4 + 2] = lg[r][g * 4 + 2] - sub;
        out[row * NCLS + g * 4 + 3] = lg[r][g * 4 + 3] - sub;
    }
}

// ---------------- launch ----------------
extern "C" void kernel_launch(void* const* d_in, const int* in_sizes, int n_in,
                              void* d_out, int out_size) {
    const float* features = (const float*)d_in[0];
    const int*   src      = (const int*)d_in[1];
    const int*   dst      = (const int*)d_in[2];
    const float* W1       = (const float*)d_in[3];
    const float* b1       = (const float*)d_in[4];
    const float* W2       = (const float*)d_in[5];
    const float* b2       = (const float*)d_in[6];
    float*       out      = (float*)d_out;

    const int NB  = (N_NODES + 255) / 256;      // 196
    const int EB  = (N_EDGES + 255) / 256;      // 3125
    const int IB  = (N_NODES * F4 + 255) / 256; // 6250
    const int PB  = (N_NODES + 7) / 8;          // 6250

    zero_deg_kernel<<<NB, 256>>>();
    deg_kernel<<<EB, 256>>>(dst);
    scan1_kernel<<<SCAN_BLOCKS, 256>>>();
    scan3_kernel<<<SCAN_BLOCKS, 256>>>();
    fill_kernel<<<EB, 256>>>(src, dst);
    init_kernel<<<IB, 256>>>((const float4*)features);

    prop_kernel<0><<<PB, 256>>>(0);   // x0 -> x1, y = feat + x1
    prop_kernel<1><<<PB, 256>>>(1);   // x1 -> x0, y += x2
    prop_kernel<2><<<PB, 256>>>(0);   // x0 -> (x3), y = (y + x3)/4

    dim3 g1((N_NODES + 127) / 128, HID / 128);  // (391, 2)
    gemm1_kernel<<<g1, 256>>>(W1, b1);

    const int G2B = (N_NODES + 31) / 32;        // 1563
    gemm2_kernel<<<G2B, 320>>>(W2, b2, out);
}

// round 9
// speedup vs baseline: 1.0354x; 1.0247x over previous
#include <cuda_runtime.h>
#include <math.h>

#define N_NODES 50000
#define N_EDGES 800000
#define F_DIM   128
#define F4      32      // float4 per feature row
#define HID     256
#define NCLS    40

#define SCAN_BLOCKS ((N_NODES + 255) / 256)   // 196

// ---------------- device scratch (static: no allocation allowed) ----------------
// RULE (learned R3-R5): never pass __device__ symbol addresses from host code —
// on GB300 the host-side shadow resolves via ATS to HOST memory. All buffer
// selection happens inside device code.
__device__ int    g_deg[N_NODES];
__device__ int    g_rowstart[N_NODES + 1];
__device__ int    g_cursor[N_NODES];
__device__ int    g_bsum[SCAN_BLOCKS];
__device__ float  g_norm[N_NODES];
__device__ int2   g_csr[N_EDGES];           // (src, norm[src] as bits)
__device__ float4 g_x0[N_NODES * F4];
__device__ float4 g_x1[N_NODES * F4];
__device__ float4 g_y [N_NODES * F4];
__device__ float4 g_h [N_NODES * (HID / 4)];

// ---------------- build: degree ----------------
__global__ void zero_deg_kernel() {
    int i = blockIdx.x * blockDim.x + threadIdx.x;
    if (i < N_NODES) g_deg[i] = 0;
}

__global__ void deg_kernel(const int* __restrict__ dst) {
    int i = blockIdx.x * blockDim.x + threadIdx.x;
    if (i < N_EDGES) atomicAdd(&g_deg[dst[i]], 1);
}

// ---------------- hierarchical scan ----------------
__device__ __forceinline__ int warp_incl_scan(int v, int lane) {
#pragma unroll
    for (int o = 1; o < 32; o <<= 1) {
        int n = __shfl_up_sync(0xffffffffu, v, o);
        if (lane >= o) v += n;
    }
    return v;
}

__device__ __forceinline__ int block_incl_scan_256(int v, int tid) {
    __shared__ int ws[8];
    int lane = tid & 31, w = tid >> 5;
    int incl = warp_incl_scan(v, lane);
    if (lane == 31) ws[w] = incl;
    __syncthreads();
    if (w == 0) {
        int s = (lane < 8) ? ws[lane] : 0;
        s = warp_incl_scan(s, lane);
        if (lane < 8) ws[lane] = s;
    }
    __syncthreads();
    if (w > 0) incl += ws[w - 1];
    return incl;
}

// phase 1: block-local exclusive scan; also computes norm = rsqrt(max(deg,1))
__global__ void scan1_kernel() {
    int tid = threadIdx.x;
    int i = blockIdx.x * 256 + tid;
    int v = (i < N_NODES) ? g_deg[i] : 0;
    if (i < N_NODES) g_norm[i] = rsqrtf((float)(v < 1 ? 1 : v));
    int incl = block_incl_scan_256(v, tid);
    if (i < N_NODES) g_rowstart[i] = incl - v;
    if (tid == 255) g_bsum[blockIdx.x] = incl;
}

// phase 2 (merged): each block reduces its own bsum prefix, adds offsets;
// ALSO streams this block's slice of features into g_x0 (init fused in)
__global__ void scan3_kernel(const float4* __restrict__ feat) {
    __shared__ int ssum[8];
    int tid = threadIdx.x;
    int bid = blockIdx.x;
    int lane = tid & 31, w = tid >> 5;

    int v = (tid < bid && tid < SCAN_BLOCKS) ? g_bsum[tid] : 0;
#pragma unroll
    for (int o = 16; o > 0; o >>= 1) v += __shfl_down_sync(0xffffffffu, v, o);
    if (lane == 0) ssum[w] = v;
    __syncthreads();
    if (tid == 0) {
        int s = 0;
#pragma unroll
        for (int i = 0; i < 8; i++) s += ssum[i];
        ssum[0] = s;
    }
    __syncthreads();
    int off = ssum[0];

    int i = bid * 256 + tid;
    if (i < N_NODES) {
        int r = g_rowstart[i] + off;
        g_rowstart[i] = r;
        g_cursor[i]   = r;
    }
    if (i == 0) g_rowstart[N_NODES] = N_EDGES;

    // fused init: coalesced copy of this block's 256 node rows (8192 float4)
    int base = bid * 256 * F4;
    int lim  = N_NODES * F4 - base;
    int n    = 256 * F4 < lim ? 256 * F4 : lim;
    for (int j = tid; j < n; j += 256)
        g_x0[base + j] = feat[base + j];
}

// fill CSR: (src, norm[src]) interleaved
__global__ void fill_kernel(const int* __restrict__ src, const int* __restrict__ dst) {
    int i = blockIdx.x * blockDim.x + threadIdx.x;
    if (i < N_EDGES) {
        int s = src[i];
        int d = dst[i];
        int pos = atomicAdd(&g_cursor[d], 1);
        int2 v;
        v.x = s;
        v.y = __float_as_int(g_norm[s]);
        g_csr[pos] = v;
    }
}

// ---------------- propagation: pull over CSR, fused y-accumulate ----------------
// block = 256 threads = 8 nodes x 32 lanes; lane owns 4 feature dims (float4)
// MODE 0 (first): y = x0[node] + acc
// MODE 1 (mid)  : y += acc
// MODE 2 (last) : y = (y + acc) * 0.25, NO xout write (x3 never needed)
template<int MODE>
__global__ void prop_kernel(int dir) {
    const float4* __restrict__ xin  = dir ? g_x1 : g_x0;
    float4*       __restrict__ xout = dir ? g_x0 : g_x1;

    int node = blockIdx.x * 8 + (threadIdx.x >> 5);
    int lane = threadIdx.x & 31;
    if (node >= N_NODES) return;

    int beg = g_rowstart[node];
    int end = g_rowstart[node + 1];

    float4 acc = make_float4(0.f, 0.f, 0.f, 0.f);
    int e = beg;
    for (; e + 4 <= end; e += 4) {
        int2 c0 = __ldg(&g_csr[e + 0]);
        int2 c1 = __ldg(&g_csr[e + 1]);
        int2 c2 = __ldg(&g_csr[e + 2]);
        int2 c3 = __ldg(&g_csr[e + 3]);
        float4 v0 = __ldg(&xin[c0.x * F4 + lane]);
        float4 v1 = __ldg(&xin[c1.x * F4 + lane]);
        float4 v2 = __ldg(&xin[c2.x * F4 + lane]);
        float4 v3 = __ldg(&xin[c3.x * F4 + lane]);
        float w0 = __int_as_float(c0.y);
        float w1 = __int_as_float(c1.y);
        float w2 = __int_as_float(c2.y);
        float w3 = __int_as_float(c3.y);
        acc.x = fmaf(v0.x, w0, acc.x); acc.y = fmaf(v0.y, w0, acc.y);
        acc.z = fmaf(v0.z, w0, acc.z); acc.w = fmaf(v0.w, w0, acc.w);
        acc.x = fmaf(v1.x, w1, acc.x); acc.y = fmaf(v1.y, w1, acc.y);
        acc.z = fmaf(v1.z, w1, acc.z); acc.w = fmaf(v1.w, w1, acc.w);
        acc.x = fmaf(v2.x, w2, acc.x); acc.y = fmaf(v2.y, w2, acc.y);
        acc.z = fmaf(v2.z, w2, acc.z); acc.w = fmaf(v2.w, w2, acc.w);
        acc.x = fmaf(v3.x, w3, acc.x); acc.y = fmaf(v3.y, w3, acc.y);
        acc.z = fmaf(v3.z, w3, acc.z); acc.w = fmaf(v3.w, w3, acc.w);
    }
    for (; e < end; e++) {
        int2 c = __ldg(&g_csr[e]);
        float w = __int_as_float(c.y);
        float4 v = __ldg(&xin[c.x * F4 + lane]);
        acc.x = fmaf(v.x, w, acc.x); acc.y = fmaf(v.y, w, acc.y);
        acc.z = fmaf(v.z, w, acc.z); acc.w = fmaf(v.w, w, acc.w);
    }

    float nd = g_norm[node];
    acc.x *= nd; acc.y *= nd; acc.z *= nd; acc.w *= nd;

    int idx = node * F4 + lane;
    if (MODE == 0) {
        xout[idx] = acc;
        float4 f = __ldg(&xin[idx]);          // features row (hot in L2)
        f.x += acc.x; f.y += acc.y; f.z += acc.z; f.w += acc.w;
        g_y[idx] = f;
    } else if (MODE == 1) {
        xout[idx] = acc;
        float4 yv = g_y[idx];
        yv.x += acc.x; yv.y += acc.y; yv.z += acc.z; yv.w += acc.w;
        g_y[idx] = yv;
    } else {
        float4 yv = g_y[idx];
        yv.x = (yv.x + acc.x) * 0.25f;
        yv.y = (yv.y + acc.y) * 0.25f;
        yv.z = (yv.z + acc.z) * 0.25f;
        yv.w = (yv.w + acc.w) * 0.25f;
        g_y[idx] = yv;                        // y now pre-scaled: feat = y
    }
}

// ---------------- GEMM1: h = relu( y @ W1 + b1 )  [50000,128]x[128,256] --------
// BM=128, BN=64, BK=16, 256 threads, 8x4 per thread (proven best config, R2)
__global__ void gemm1_kernel(const float* __restrict__ W1, const float* __restrict__ b1) {
    __shared__ float As[16][132];   // [k][m], padded
    __shared__ float Bs[16][64];    // [k][n]

    int tid = threadIdx.x;
    int m0 = blockIdx.x * 128;
    int n0 = blockIdx.y * 64;
    int ty = tid >> 4;          // 0..15 -> 8 rows each
    int tx = tid & 15;          // 0..15 -> 4 cols each

    const float* y = (const float*)g_y;

    int arow = tid >> 1;            // 0..127
    int ak   = (tid & 1) * 8;       // 0 or 8
    int brow = tid >> 4;            // 0..15
    int bc   = (tid & 15) * 4;      // 0..60

    float acc[8][4];
#pragma unroll
    for (int i = 0; i < 8; i++)
#pragma unroll
        for (int j = 0; j < 4; j++) acc[i][j] = 0.f;

    for (int k0 = 0; k0 < F_DIM; k0 += 16) {
        int gm = m0 + arow;
        float4 av0 = make_float4(0.f, 0.f, 0.f, 0.f);
        float4 av1 = make_float4(0.f, 0.f, 0.f, 0.f);
        if (gm < N_NODES) {
            av0 = *(const float4*)&y[gm * F_DIM + k0 + ak];
            av1 = *(const float4*)&y[gm * F_DIM + k0 + ak + 4];
        }
        As[ak + 0][arow] = av0.x;
        As[ak + 1][arow] = av0.y;
        As[ak + 2][arow] = av0.z;
        As[ak + 3][arow] = av0.w;
        As[ak + 4][arow] = av1.x;
        As[ak + 5][arow] = av1.y;
        As[ak + 6][arow] = av1.z;
        As[ak + 7][arow] = av1.w;

        float4 bv = *(const float4*)&W1[(k0 + brow) * HID + n0 + bc];
        *(float4*)&Bs[brow][bc] = bv;

        __syncthreads();
#pragma unroll
        for (int kk = 0; kk < 16; kk++) {
            float4 a0 = *(const float4*)&As[kk][ty * 8];
            float4 a1 = *(const float4*)&As[kk][ty * 8 + 4];
            float4 b4 = *(const float4*)&Bs[kk][tx * 4];
            float a_[8] = {a0.x, a0.y, a0.z, a0.w, a1.x, a1.y, a1.z, a1.w};
            float b_[4] = {b4.x, b4.y, b4.z, b4.w};
#pragma unroll
            for (int i = 0; i < 8; i++)
#pragma unroll
                for (int j = 0; j < 4; j++)
                    acc[i][j] = fmaf(a_[i], b_[j], acc[i][j]);
        }
        __syncthreads();
    }

    float4 bias = *(const float4*)&b1[n0 + tx * 4];
    float* h = (float*)g_h;
#pragma unroll
    for (int i = 0; i < 8; i++) {
        int gm = m0 + ty * 8 + i;
        if (gm < N_NODES) {
            float4 o;
            o.x = fmaxf(acc[i][0] + bias.x, 0.f);
            o.y = fmaxf(acc[i][1] + bias.y, 0.f);
            o.z = fmaxf(acc[i][2] + bias.z, 0.f);
            o.w = fmaxf(acc[i][3] + bias.w, 0.f);
            *(float4*)&h[gm * HID + n0 + tx * 4] = o;
        }
    }
}

// ---------------- GEMM2 + log_softmax fused: out = logsoftmax(h @ W2 + b2) -------
__global__ void gemm2_kernel(const float* __restrict__ W2, const float* __restrict__ b2,
                             float* __restrict__ out) {
    __shared__ float w2c[32][44];
    __shared__ float hc[32][33];
    __shared__ float lg[32][41];
    __shared__ float rm[32], rs[32];

    int tid = threadIdx.x;          // 0..319
    int r = tid / 10;               // 0..31
    int g = tid % 10;               // 0..9  -> classes 4g..4g+3
    int m0 = blockIdx.x * 32;

    const float* h = (const float*)g_h;

    float a0 = 0.f, a1 = 0.f, a2 = 0.f, a3 = 0.f;

    for (int kb = 0; kb < HID; kb += 32) {
        for (int idx = tid; idx < 32 * 32; idx += 320) {
            int rr = idx >> 5, kk = idx & 31;
            int row = m0 + rr;
            hc[rr][kk] = (row < N_NODES) ? h[row * HID + kb + kk] : 0.f;
        }
        for (int idx = tid; idx < 32 * 40; idx += 320) {
            int kk = idx / 40, cc = idx % 40;
            w2c[kk][cc] = W2[(kb + kk) * NCLS + cc];
        }
        __syncthreads();
#pragma unroll
        for (int kk = 0; kk < 32; kk++) {
            float hv = hc[r][kk];
            float4 wv = *(const float4*)&w2c[kk][g * 4];
            a0 = fmaf(hv, wv.x, a0);
            a1 = fmaf(hv, wv.y, a1);
            a2 = fmaf(hv, wv.z, a2);
            a3 = fmaf(hv, wv.w, a3);
        }
        __syncthreads();
    }

    lg[r][g * 4 + 0] = a0 + b2[g * 4 + 0];
    lg[r][g * 4 + 1] = a1 + b2[g * 4 + 1];
    lg[r][g * 4 + 2] = a2 + b2[g * 4 + 2];
    lg[r][g * 4 + 3] = a3 + b2[g * 4 + 3];
    __syncthreads();

    if (tid < 32) {
        float m = -1e30f;
#pragma unroll
        for (int c = 0; c < NCLS; c++) m = fmaxf(m, lg[tid][c]);
        float s = 0.f;
#pragma unroll
        for (int c = 0; c < NCLS; c++) s += expf(lg[tid][c] - m);
        rm[tid] = m;
        rs[tid] = logf(s);
    }
    __syncthreads();

    int row = m0 + r;
    if (row < N_NODES) {
        float sub = rm[r] + rs[r];
        out[row * NCLS + g * 4 + 0] = lg[r][g * 4 + 0] - sub;
        out[row * NCLS + g * 4 + 1] = lg[r][g * 4 + 1] - sub;
        out[row * NCLS + g * 4 + 2] = lg[r][g * 4 + 2] - sub;
        out[row * NCLS + g * 4 + 3] = lg[r][g * 4 + 3] - sub;
    }
}

// ---------------- launch ----------------
// NOTE: ncu capture is "-s 5 -c 1" → it profiles the 6th launch. Launch order
// below deliberately places prop_kernel<0> (the dominant kernel) 6th.
extern "C" void kernel_launch(void* const* d_in, const int* in_sizes, int n_in,
                              void* d_out, int out_size) {
    const float* features = (const float*)d_in[0];
    const int*   src      = (const int*)d_in[1];
    const int*   dst      = (const int*)d_in[2];
    const float* W1       = (const float*)d_in[3];
    const float* b1       = (const float*)d_in[4];
    const float* W2       = (const float*)d_in[5];
    const float* b2       = (const float*)d_in[6];
    float*       out      = (float*)d_out;

    const int NB  = (N_NODES + 255) / 256;      // 196
    const int EB  = (N_EDGES + 255) / 256;      // 3125
    const int PB  = (N_NODES + 7) / 8;          // 6250

    zero_deg_kernel<<<NB, 256>>>();                               // 1
    deg_kernel<<<EB, 256>>>(dst);                                 // 2
    scan1_kernel<<<SCAN_BLOCKS, 256>>>();                         // 3
    scan3_kernel<<<SCAN_BLOCKS, 256>>>((const float4*)features);  // 4 (+init fused)
    fill_kernel<<<EB, 256>>>(src, dst);                           // 5

    prop_kernel<0><<<PB, 256>>>(0);   // 6  <- profiled by ncu -s 5 -c 1
    prop_kernel<1><<<PB, 256>>>(1);   // 7
    prop_kernel<2><<<PB, 256>>>(0);   // 8

    dim3 g1((N_NODES + 127) / 128, HID / 64);   // (391, 4)
    gemm1_kernel<<<g1, 256>>>(W1, b1);          // 9

    const int G2B = (N_NODES + 31) / 32;        // 1563
    gemm2_kernel<<<G2B, 320>>>(W2, b2, out);    // 10
}

// round 10
// speedup vs baseline: 1.1350x; 1.0962x over previous
#include <cuda_runtime.h>
#include <math.h>

#define N_NODES 50000
#define N_EDGES 800000
#define F_DIM   128
#define F4      32      // float4 per feature row
#define HID     256
#define NCLS    40

#define SCAN_BLOCKS ((N_NODES + 255) / 256)   // 196

// ---------------- device scratch (static: no allocation allowed) ----------------
// RULE (learned R3-R5): never pass __device__ symbol addresses from host code —
// on GB300 the host-side shadow resolves via ATS to HOST memory. All buffer
// selection happens inside device code.
__device__ int    g_deg[N_NODES];
__device__ int    g_rowstart[N_NODES + 1];
__device__ int    g_cursor[N_NODES];
__device__ int    g_bsum[SCAN_BLOCKS];
__device__ float  g_norm[N_NODES];
__device__ int2   g_csr[N_EDGES];           // (src, norm[src] as bits)
__device__ float4 g_x0[N_NODES * F4];
__device__ float4 g_x1[N_NODES * F4];
__device__ float4 g_y [N_NODES * F4];
__device__ float4 g_h [N_NODES * (HID / 4)];

// ---------------- build: degree ----------------
__global__ void zero_deg_kernel() {
    int i = blockIdx.x * blockDim.x + threadIdx.x;
    if (i < N_NODES) g_deg[i] = 0;
}

__global__ void deg_kernel(const int* __restrict__ dst) {
    int i = blockIdx.x * blockDim.x + threadIdx.x;
    if (i < N_EDGES) atomicAdd(&g_deg[dst[i]], 1);
}

// ---------------- hierarchical scan ----------------
__device__ __forceinline__ int warp_incl_scan(int v, int lane) {
#pragma unroll
    for (int o = 1; o < 32; o <<= 1) {
        int n = __shfl_up_sync(0xffffffffu, v, o);
        if (lane >= o) v += n;
    }
    return v;
}

__device__ __forceinline__ int block_incl_scan_256(int v, int tid) {
    __shared__ int ws[8];
    int lane = tid & 31, w = tid >> 5;
    int incl = warp_incl_scan(v, lane);
    if (lane == 31) ws[w] = incl;
    __syncthreads();
    if (w == 0) {
        int s = (lane < 8) ? ws[lane] : 0;
        s = warp_incl_scan(s, lane);
        if (lane < 8) ws[lane] = s;
    }
    __syncthreads();
    if (w > 0) incl += ws[w - 1];
    return incl;
}

// phase 1: block-local exclusive scan; also computes norm = rsqrt(max(deg,1))
__global__ void scan1_kernel() {
    int tid = threadIdx.x;
    int i = blockIdx.x * 256 + tid;
    int v = (i < N_NODES) ? g_deg[i] : 0;
    if (i < N_NODES) g_norm[i] = rsqrtf((float)(v < 1 ? 1 : v));
    int incl = block_incl_scan_256(v, tid);
    if (i < N_NODES) g_rowstart[i] = incl - v;
    if (tid == 255) g_bsum[blockIdx.x] = incl;
}

// phase 2 (merged): each block reduces its own bsum prefix, adds offsets;
// ALSO streams this block's slice of features into g_x0 (init fused in)
__global__ void scan3_kernel(const float4* __restrict__ feat) {
    __shared__ int ssum[8];
    int tid = threadIdx.x;
    int bid = blockIdx.x;
    int lane = tid & 31, w = tid >> 5;

    int v = (tid < bid && tid < SCAN_BLOCKS) ? g_bsum[tid] : 0;
#pragma unroll
    for (int o = 16; o > 0; o >>= 1) v += __shfl_down_sync(0xffffffffu, v, o);
    if (lane == 0) ssum[w] = v;
    __syncthreads();
    if (tid == 0) {
        int s = 0;
#pragma unroll
        for (int i = 0; i < 8; i++) s += ssum[i];
        ssum[0] = s;
    }
    __syncthreads();
    int off = ssum[0];

    int i = bid * 256 + tid;
    if (i < N_NODES) {
        int r = g_rowstart[i] + off;
        g_rowstart[i] = r;
        g_cursor[i]   = r;
    }
    if (i == 0) g_rowstart[N_NODES] = N_EDGES;

    // fused init: coalesced copy of this block's 256 node rows (8192 float4)
    int base = bid * 256 * F4;
    int lim  = N_NODES * F4 - base;
    int n    = 256 * F4 < lim ? 256 * F4 : lim;
    for (int j = tid; j < n; j += 256)
        g_x0[base + j] = feat[base + j];
}

// fill CSR: (src, norm[src]) interleaved
__global__ void fill_kernel(const int* __restrict__ src, const int* __restrict__ dst) {
    int i = blockIdx.x * blockDim.x + threadIdx.x;
    if (i < N_EDGES) {
        int s = src[i];
        int d = dst[i];
        int pos = atomicAdd(&g_cursor[d], 1);
        int2 v;
        v.x = s;
        v.y = __float_as_int(g_norm[s]);
        g_csr[pos] = v;
    }
}

// ---------------- propagation: pull over CSR, fused y-accumulate ----------------
// block = 256 threads = 8 nodes x 32 lanes; lane owns 4 feature dims (float4)
// MODE 0 (first): y = x0[node] + acc
// MODE 1 (mid)  : y += acc
// MODE 2 (last) : y = (y + acc) * 0.25, NO xout write (x3 never needed)
template<int MODE>
__global__ void prop_kernel(int dir) {
    const float4* __restrict__ xin  = dir ? g_x1 : g_x0;
    float4*       __restrict__ xout = dir ? g_x0 : g_x1;

    int node = blockIdx.x * 8 + (threadIdx.x >> 5);
    int lane = threadIdx.x & 31;
    if (node >= N_NODES) return;

    int beg = g_rowstart[node];
    int end = g_rowstart[node + 1];

    float4 acc = make_float4(0.f, 0.f, 0.f, 0.f);
    int e = beg;
    for (; e + 4 <= end; e += 4) {
        int2 c0 = __ldg(&g_csr[e + 0]);
        int2 c1 = __ldg(&g_csr[e + 1]);
        int2 c2 = __ldg(&g_csr[e + 2]);
        int2 c3 = __ldg(&g_csr[e + 3]);
        float4 v0 = __ldg(&xin[c0.x * F4 + lane]);
        float4 v1 = __ldg(&xin[c1.x * F4 + lane]);
        float4 v2 = __ldg(&xin[c2.x * F4 + lane]);
        float4 v3 = __ldg(&xin[c3.x * F4 + lane]);
        float w0 = __int_as_float(c0.y);
        float w1 = __int_as_float(c1.y);
        float w2 = __int_as_float(c2.y);
        float w3 = __int_as_float(c3.y);
        acc.x = fmaf(v0.x, w0, acc.x); acc.y = fmaf(v0.y, w0, acc.y);
        acc.z = fmaf(v0.z, w0, acc.z); acc.w = fmaf(v0.w, w0, acc.w);
        acc.x = fmaf(v1.x, w1, acc.x); acc.y = fmaf(v1.y, w1, acc.y);
        acc.z = fmaf(v1.z, w1, acc.z); acc.w = fmaf(v1.w, w1, acc.w);
        acc.x = fmaf(v2.x, w2, acc.x); acc.y = fmaf(v2.y, w2, acc.y);
        acc.z = fmaf(v2.z, w2, acc.z); acc.w = fmaf(v2.w, w2, acc.w);
        acc.x = fmaf(v3.x, w3, acc.x); acc.y = fmaf(v3.y, w3, acc.y);
        acc.z = fmaf(v3.z, w3, acc.z); acc.w = fmaf(v3.w, w3, acc.w);
    }
    for (; e < end; e++) {
        int2 c = __ldg(&g_csr[e]);
        float w = __int_as_float(c.y);
        float4 v = __ldg(&xin[c.x * F4 + lane]);
        acc.x = fmaf(v.x, w, acc.x); acc.y = fmaf(v.y, w, acc.y);
        acc.z = fmaf(v.z, w, acc.z); acc.w = fmaf(v.w, w, acc.w);
    }

    float nd = g_norm[node];
    acc.x *= nd; acc.y *= nd; acc.z *= nd; acc.w *= nd;

    int idx = node * F4 + lane;
    if (MODE == 0) {
        xout[idx] = acc;
        float4 f = __ldg(&xin[idx]);          // features row (hot in L2)
        f.x += acc.x; f.y += acc.y; f.z += acc.z; f.w += acc.w;
        g_y[idx] = f;
    } else if (MODE == 1) {
        xout[idx] = acc;
        float4 yv = g_y[idx];
        yv.x += acc.x; yv.y += acc.y; yv.z += acc.z; yv.w += acc.w;
        g_y[idx] = yv;
    } else {
        float4 yv = g_y[idx];
        yv.x = (yv.x + acc.x) * 0.25f;
        yv.y = (yv.y + acc.y) * 0.25f;
        yv.z = (yv.z + acc.z) * 0.25f;
        yv.w = (yv.w + acc.w) * 0.25f;
        g_y[idx] = yv;                        // y now pre-scaled: feat = y
    }
}

// ---------------- GEMM1 (tf32 single-pass): h = relu( y @ W1 + b1 ) -------------
// BM=64, BN=128, BK=16, 256 threads = 8 warps (2m x 4n), warp tile 32x32
// Layout identical to R7's verified tf32x3 kernel, minus the lo-half passes.
__device__ __forceinline__ float tf32_rna(float a) {
    unsigned r;
    asm("cvt.rna.tf32.f32 %0, %1;" : "=r"(r) : "f"(a));
    return __uint_as_float(r);
}

#define MMA_TF32(D, A, B) \
    asm volatile("mma.sync.aligned.m16n8k8.row.col.f32.tf32.tf32.f32 " \
        "{%0,%1,%2,%3}, {%4,%5,%6,%7}, {%8,%9}, {%0,%1,%2,%3};" \
        : "+f"((D)[0]), "+f"((D)[1]), "+f"((D)[2]), "+f"((D)[3]) \
        : "r"((A)[0]), "r"((A)[1]), "r"((A)[2]), "r"((A)[3]), \
          "r"((B)[0]), "r"((B)[1]))

__global__ __launch_bounds__(256) void gemm1_kernel(const float* __restrict__ W1,
                                                    const float* __restrict__ b1) {
    __shared__ float As[16][68];    // [k][m]  tf32 values
    __shared__ float Bs[16][132];   // [k][n]  tf32 values

    int tid  = threadIdx.x;
    int lane = tid & 31;
    int wid  = tid >> 5;
    int warp_m = wid & 1;            // 0..1 -> 32 rows each
    int warp_n = wid >> 1;           // 0..3 -> 32 cols each
    int qrow = lane >> 2;            // 0..7
    int qcol = lane & 3;             // 0..3

    int m0 = blockIdx.x * 64;
    int n0 = blockIdx.y * 128;

    const float* y = (const float*)g_y;

    int arow = tid >> 2;             // 0..63
    int ak   = (tid & 3) * 4;        // 0,4,8,12
    int brow = tid >> 4;             // 0..15
    int bc   = (tid & 15) * 8;       // 0..120

    float d[2][4][4];
#pragma unroll
    for (int t = 0; t < 2; t++)
#pragma unroll
        for (int u = 0; u < 4; u++)
#pragma unroll
            for (int i = 0; i < 4; i++) d[t][u][i] = 0.f;

    for (int k0 = 0; k0 < F_DIM; k0 += 16) {
        // stage A (64 x 16) as tf32
        {
            int gm = m0 + arow;
            float4 av = make_float4(0.f, 0.f, 0.f, 0.f);
            if (gm < N_NODES) av = *(const float4*)&y[gm * F_DIM + k0 + ak];
            As[ak + 0][arow] = tf32_rna(av.x);
            As[ak + 1][arow] = tf32_rna(av.y);
            As[ak + 2][arow] = tf32_rna(av.z);
            As[ak + 3][arow] = tf32_rna(av.w);
        }
        // stage B (16 x 128) as tf32
        {
            const float* wrow = &W1[(k0 + brow) * HID + n0 + bc];
            float4 bv0 = *(const float4*)&wrow[0];
            float4 bv1 = *(const float4*)&wrow[4];
            Bs[brow][bc + 0] = tf32_rna(bv0.x);
            Bs[brow][bc + 1] = tf32_rna(bv0.y);
            Bs[brow][bc + 2] = tf32_rna(bv0.z);
            Bs[brow][bc + 3] = tf32_rna(bv0.w);
            Bs[brow][bc + 4] = tf32_rna(bv1.x);
            Bs[brow][bc + 5] = tf32_rna(bv1.y);
            Bs[brow][bc + 6] = tf32_rna(bv1.z);
            Bs[brow][bc + 7] = tf32_rna(bv1.w);
        }
        __syncthreads();

#pragma unroll
        for (int k8 = 0; k8 < 16; k8 += 8) {
            unsigned a[2][4], b[4][2];
            int kA = k8 + qcol;
#pragma unroll
            for (int t = 0; t < 2; t++) {
                int mr = warp_m * 32 + t * 16 + qrow;
                a[t][0] = __float_as_uint(As[kA][mr]);
                a[t][1] = __float_as_uint(As[kA][mr + 8]);
                a[t][2] = __float_as_uint(As[kA + 4][mr]);
                a[t][3] = __float_as_uint(As[kA + 4][mr + 8]);
            }
#pragma unroll
            for (int u = 0; u < 4; u++) {
                int bcol = warp_n * 32 + u * 8 + qrow;
                b[u][0] = __float_as_uint(Bs[kA][bcol]);
                b[u][1] = __float_as_uint(Bs[kA + 4][bcol]);
            }
#pragma unroll
            for (int t = 0; t < 2; t++)
#pragma unroll
                for (int u = 0; u < 4; u++)
                    MMA_TF32(d[t][u], a[t], b[u]);
        }
        __syncthreads();
    }

    // epilogue: bias + relu + store
    float* h = (float*)g_h;
#pragma unroll
    for (int t = 0; t < 2; t++) {
        int r0 = m0 + warp_m * 32 + t * 16 + qrow;
#pragma unroll
        for (int u = 0; u < 4; u++) {
            int c = n0 + warp_n * 32 + u * 8 + qcol * 2;
            float2 bb = *(const float2*)&b1[c];
            if (r0 < N_NODES) {
                float2 o;
                o.x = fmaxf(d[t][u][0] + bb.x, 0.f);
                o.y = fmaxf(d[t][u][1] + bb.y, 0.f);
                *(float2*)&h[r0 * HID + c] = o;
            }
            if (r0 + 8 < N_NODES) {
                float2 o;
                o.x = fmaxf(d[t][u][2] + bb.x, 0.f);
                o.y = fmaxf(d[t][u][3] + bb.y, 0.f);
                *(float2*)&h[(r0 + 8) * HID + c] = o;
            }
        }
    }
}

// ---------------- GEMM2 + log_softmax fused: out = logsoftmax(h @ W2 + b2) -------
__global__ void gemm2_kernel(const float* __restrict__ W2, const float* __restrict__ b2,
                             float* __restrict__ out) {
    __shared__ float w2c[32][44];
    __shared__ float hc[32][33];
    __shared__ float lg[32][41];
    __shared__ float rm[32], rs[32];

    int tid = threadIdx.x;          // 0..319
    int r = tid / 10;               // 0..31
    int g = tid % 10;               // 0..9  -> classes 4g..4g+3
    int m0 = blockIdx.x * 32;

    const float* h = (const float*)g_h;

    float a0 = 0.f, a1 = 0.f, a2 = 0.f, a3 = 0.f;

    for (int kb = 0; kb < HID; kb += 32) {
        for (int idx = tid; idx < 32 * 32; idx += 320) {
            int rr = idx >> 5, kk = idx & 31;
            int row = m0 + rr;
            hc[rr][kk] = (row < N_NODES) ? h[row * HID + kb + kk] : 0.f;
        }
        for (int idx = tid; idx < 32 * 40; idx += 320) {
            int kk = idx / 40, cc = idx % 40;
            w2c[kk][cc] = W2[(kb + kk) * NCLS + cc];
        }
        __syncthreads();
#pragma unroll
        for (int kk = 0; kk < 32; kk++) {
            float hv = hc[r][kk];
            float4 wv = *(const float4*)&w2c[kk][g * 4];
            a0 = fmaf(hv, wv.x, a0);
            a1 = fmaf(hv, wv.y, a1);
            a2 = fmaf(hv, wv.z, a2);
            a3 = fmaf(hv, wv.w, a3);
        }
        __syncthreads();
    }

    lg[r][g * 4 + 0] = a0 + b2[g * 4 + 0];
    lg[r][g * 4 + 1] = a1 + b2[g * 4 + 1];
    lg[r][g * 4 + 2] = a2 + b2[g * 4 + 2];
    lg[r][g * 4 + 3] = a3 + b2[g * 4 + 3];
    __syncthreads();

    if (tid < 32) {
        float m = -1e30f;
#pragma unroll
        for (int c = 0; c < NCLS; c++) m = fmaxf(m, lg[tid][c]);
        float s = 0.f;
#pragma unroll
        for (int c = 0; c < NCLS; c++) s += expf(lg[tid][c] - m);
        rm[tid] = m;
        rs[tid] = logf(s);
    }
    __syncthreads();

    int row = m0 + r;
    if (row < N_NODES) {
        float sub = rm[r] + rs[r];
        out[row * NCLS + g * 4 + 0] = lg[r][g * 4 + 0] - sub;
        out[row * NCLS + g * 4 + 1] = lg[r][g * 4 + 1] - sub;
        out[row * NCLS + g * 4 + 2] = lg[r][g * 4 + 2] - sub;
        out[row * NCLS + g * 4 + 3] = lg[r][g * 4 + 3] - sub;
    }
}

// ---------------- launch ----------------
extern "C" void kernel_launch(void* const* d_in, const int* in_sizes, int n_in,
                              void* d_out, int out_size) {
    const float* features = (const float*)d_in[0];
    const int*   src      = (const int*)d_in[1];
    const int*   dst      = (const int*)d_in[2];
    const float* W1       = (const float*)d_in[3];
    const float* b1       = (const float*)d_in[4];
    const float* W2       = (const float*)d_in[5];
    const float* b2       = (const float*)d_in[6];
    float*       out      = (float*)d_out;

    const int NB  = (N_NODES + 255) / 256;      // 196
    const int EB  = (N_EDGES + 255) / 256;      // 3125
    const int PB  = (N_NODES + 7) / 8;          // 6250

    zero_deg_kernel<<<NB, 256>>>();                               // 1
    deg_kernel<<<EB, 256>>>(dst);                                 // 2
    scan1_kernel<<<SCAN_BLOCKS, 256>>>();                         // 3
    scan3_kernel<<<SCAN_BLOCKS, 256>>>((const float4*)features);  // 4 (+init fused)
    fill_kernel<<<EB, 256>>>(src, dst);                           // 5

    prop_kernel<0><<<PB, 256>>>(0);   // 6  <- profiled by ncu -s 5 -c 1
    prop_kernel<1><<<PB, 256>>>(1);   // 7
    prop_kernel<2><<<PB, 256>>>(0);   // 8

    dim3 g1((N_NODES + 63) / 64, HID / 128);    // (782, 2)
    gemm1_kernel<<<g1, 256>>>(W1, b1);          // 9

    const int G2B = (N_NODES + 31) / 32;        // 1563
    gemm2_kernel<<<G2B, 320>>>(W2, b2, out);    // 10
}

// round 11
// speedup vs baseline: 1.7828x; 1.5707x over previous
#include <cuda_runtime.h>
#include <cuda_fp16.h>
#include <math.h>

#define N_NODES 50000
#define N_EDGES 800000
#define F_DIM   128
#define F4      32      // float4 per feature row
#define HID     256
#define NCLS    40

#define SCAN_BLOCKS ((N_NODES + 255) / 256)   // 196

// ---------------- device scratch (static: no allocation allowed) ----------------
// RULE (learned R3-R5): never pass __device__ symbol addresses from host code —
// on GB300 the host-side shadow resolves via ATS to HOST memory. All buffer
// selection happens inside device code.
__device__ int    g_deg[N_NODES];
__device__ int    g_rowstart[N_NODES + 1];
__device__ int    g_cursor[N_NODES];
__device__ int    g_bsum[SCAN_BLOCKS];
__device__ float  g_norm[N_NODES];
__device__ int2   g_csr[N_EDGES];           // (src, norm[src] as bits)
__device__ __half g_xh0[N_NODES * F_DIM];   // fp16 ping
__device__ __half g_xh1[N_NODES * F_DIM];   // fp16 pong
__device__ float4 g_y [N_NODES * F4];       // fp32 running sum
__device__ float4 g_h [N_NODES * (HID / 4)];

// ---------------- build: degree ----------------
__global__ void zero_deg_kernel() {
    int i = blockIdx.x * blockDim.x + threadIdx.x;
    if (i < N_NODES) g_deg[i] = 0;
}

__global__ void deg_kernel(const int* __restrict__ dst) {
    int i = blockIdx.x * blockDim.x + threadIdx.x;
    if (i < N_EDGES) atomicAdd(&g_deg[dst[i]], 1);
}

// ---------------- hierarchical scan ----------------
__device__ __forceinline__ int warp_incl_scan(int v, int lane) {
#pragma unroll
    for (int o = 1; o < 32; o <<= 1) {
        int n = __shfl_up_sync(0xffffffffu, v, o);
        if (lane >= o) v += n;
    }
    return v;
}

__device__ __forceinline__ int block_incl_scan_256(int v, int tid) {
    __shared__ int ws[8];
    int lane = tid & 31, w = tid >> 5;
    int incl = warp_incl_scan(v, lane);
    if (lane == 31) ws[w] = incl;
    __syncthreads();
    if (w == 0) {
        int s = (lane < 8) ? ws[lane] : 0;
        s = warp_incl_scan(s, lane);
        if (lane < 8) ws[lane] = s;
    }
    __syncthreads();
    if (w > 0) incl += ws[w - 1];
    return incl;
}

// phase 1: block-local exclusive scan; also computes norm = rsqrt(max(deg,1))
__global__ void scan1_kernel() {
    int tid = threadIdx.x;
    int i = blockIdx.x * 256 + tid;
    int v = (i < N_NODES) ? g_deg[i] : 0;
    if (i < N_NODES) g_norm[i] = rsqrtf((float)(v < 1 ? 1 : v));
    int incl = block_incl_scan_256(v, tid);
    if (i < N_NODES) g_rowstart[i] = incl - v;
    if (tid == 255) g_bsum[blockIdx.x] = incl;
}

// phase 2 (merged): bsum prefix per block, add offsets; ALSO convert this
// block's feature slice into fp16 g_xh0 (init fused in)
__global__ void scan3_kernel(const float4* __restrict__ feat) {
    __shared__ int ssum[8];
    int tid = threadIdx.x;
    int bid = blockIdx.x;
    int lane = tid & 31, w = tid >> 5;

    int v = (tid < bid && tid < SCAN_BLOCKS) ? g_bsum[tid] : 0;
#pragma unroll
    for (int o = 16; o > 0; o >>= 1) v += __shfl_down_sync(0xffffffffu, v, o);
    if (lane == 0) ssum[w] = v;
    __syncthreads();
    if (tid == 0) {
        int s = 0;
#pragma unroll
        for (int i = 0; i < 8; i++) s += ssum[i];
        ssum[0] = s;
    }
    __syncthreads();
    int off = ssum[0];

    int i = bid * 256 + tid;
    if (i < N_NODES) {
        int r = g_rowstart[i] + off;
        g_rowstart[i] = r;
        g_cursor[i]   = r;
    }
    if (i == 0) g_rowstart[N_NODES] = N_EDGES;

    // fused init: convert this block's 256 node rows to fp16 (float4 -> uint2)
    uint2* xh0v = (uint2*)g_xh0;     // one uint2 = 4 halves, same index as float4
    int base = bid * 256 * F4;
    int lim  = N_NODES * F4 - base;
    int n    = 256 * F4 < lim ? 256 * F4 : lim;
    for (int j = tid; j < n; j += 256) {
        float4 f = feat[base + j];
        __half2 h0 = __floats2half2_rn(f.x, f.y);
        __half2 h1 = __floats2half2_rn(f.z, f.w);
        uint2 u;
        u.x = *(unsigned*)&h0;
        u.y = *(unsigned*)&h1;
        xh0v[base + j] = u;
    }
}

// fill CSR: (src, norm[src]) interleaved
__global__ void fill_kernel(const int* __restrict__ src, const int* __restrict__ dst) {
    int i = blockIdx.x * blockDim.x + threadIdx.x;
    if (i < N_EDGES) {
        int s = src[i];
        int d = dst[i];
        int pos = atomicAdd(&g_cursor[d], 1);
        int2 v;
        v.x = s;
        v.y = __float_as_int(g_norm[s]);
        g_csr[pos] = v;
    }
}

// ---------------- propagation: pull over fp16 CSR gather, fp32 accumulate -------
// block = 256 threads = 8 nodes x 32 lanes; lane owns 4 feature dims (8B fp16)
// MODE 0 (first): y = feat(fp32 input, coalesced) + acc
// MODE 1 (mid)  : y += acc
// MODE 2 (last) : y = (y + acc) * 0.25, NO xout write
__device__ __forceinline__ void gacc(uint2 u, float w, float4& acc) {
    float2 f0 = __half22float2(*(__half2*)&u.x);
    float2 f1 = __half22float2(*(__half2*)&u.y);
    acc.x = fmaf(f0.x, w, acc.x);
    acc.y = fmaf(f0.y, w, acc.y);
    acc.z = fmaf(f1.x, w, acc.z);
    acc.w = fmaf(f1.y, w, acc.w);
}

template<int MODE>
__global__ void prop_kernel(int dir, const float4* __restrict__ feat) {
    const __half* __restrict__ xin  = dir ? g_xh1 : g_xh0;
    __half*       __restrict__ xout = dir ? g_xh0 : g_xh1;

    int node = blockIdx.x * 8 + (threadIdx.x >> 5);
    int lane = threadIdx.x & 31;
    if (node >= N_NODES) return;

    int beg = g_rowstart[node];
    int end = g_rowstart[node + 1];
    int lane4 = lane * 4;

    float4 acc = make_float4(0.f, 0.f, 0.f, 0.f);
    int e = beg;
    for (; e + 4 <= end; e += 4) {
        int2 c0 = __ldg(&g_csr[e + 0]);
        int2 c1 = __ldg(&g_csr[e + 1]);
        int2 c2 = __ldg(&g_csr[e + 2]);
        int2 c3 = __ldg(&g_csr[e + 3]);
        uint2 u0 = __ldg((const uint2*)(xin + c0.x * F_DIM + lane4));
        uint2 u1 = __ldg((const uint2*)(xin + c1.x * F_DIM + lane4));
        uint2 u2 = __ldg((const uint2*)(xin + c2.x * F_DIM + lane4));
        uint2 u3 = __ldg((const uint2*)(xin + c3.x * F_DIM + lane4));
        gacc(u0, __int_as_float(c0.y), acc);
        gacc(u1, __int_as_float(c1.y), acc);
        gacc(u2, __int_as_float(c2.y), acc);
        gacc(u3, __int_as_float(c3.y), acc);
    }
    for (; e < end; e++) {
        int2 c = __ldg(&g_csr[e]);
        uint2 u = __ldg((const uint2*)(xin + c.x * F_DIM + lane4));
        gacc(u, __int_as_float(c.y), acc);
    }

    float nd = g_norm[node];
    acc.x *= nd; acc.y *= nd; acc.z *= nd; acc.w *= nd;

    int idx = node * F4 + lane;
    if (MODE != 2) {
        __half2 o0 = __floats2half2_rn(acc.x, acc.y);
        __half2 o1 = __floats2half2_rn(acc.z, acc.w);
        uint2 u;
        u.x = *(unsigned*)&o0;
        u.y = *(unsigned*)&o1;
        *(uint2*)(xout + node * F_DIM + lane4) = u;
    }

    if (MODE == 0) {
        float4 f = __ldg(&feat[idx]);         // fp32 features, coalesced stream
        f.x += acc.x; f.y += acc.y; f.z += acc.z; f.w += acc.w;
        g_y[idx] = f;
    } else if (MODE == 1) {
        float4 yv = g_y[idx];
        yv.x += acc.x; yv.y += acc.y; yv.z += acc.z; yv.w += acc.w;
        g_y[idx] = yv;
    } else {
        float4 yv = g_y[idx];
        yv.x = (yv.x + acc.x) * 0.25f;
        yv.y = (yv.y + acc.y) * 0.25f;
        yv.z = (yv.z + acc.z) * 0.25f;
        yv.w = (yv.w + acc.w) * 0.25f;
        g_y[idx] = yv;                        // y pre-scaled: feat = y
    }
}

// ---------------- tf32 helpers --------------------------------------------------
__device__ __forceinline__ float tf32_rna(float a) {
    unsigned r;
    asm("cvt.rna.tf32.f32 %0, %1;" : "=r"(r) : "f"(a));
    return __uint_as_float(r);
}

#define MMA_TF32(D, A, B) \
    asm volatile("mma.sync.aligned.m16n8k8.row.col.f32.tf32.tf32.f32 " \
        "{%0,%1,%2,%3}, {%4,%5,%6,%7}, {%8,%9}, {%0,%1,%2,%3};" \
        : "+f"((D)[0]), "+f"((D)[1]), "+f"((D)[2]), "+f"((D)[3]) \
        : "r"((A)[0]), "r"((A)[1]), "r"((A)[2]), "r"((A)[3]), \
          "r"((B)[0]), "r"((B)[1]))

// ---------------- GEMM1 (tf32 single-pass): h = relu( y @ W1 + b1 ) -------------
// BM=64, BN=128, BK=16, 256 threads = 8 warps (2m x 4n), warp tile 32x32
__global__ __launch_bounds__(256) void gemm1_kernel(const float* __restrict__ W1,
                                                    const float* __restrict__ b1) {
    __shared__ float As[16][68];    // [k][m]  tf32 values
    __shared__ float Bs[16][132];   // [k][n]  tf32 values

    int tid  = threadIdx.x;
    int lane = tid & 31;
    int wid  = tid >> 5;
    int warp_m = wid & 1;
    int warp_n = wid >> 1;
    int qrow = lane >> 2;
    int qcol = lane & 3;

    int m0 = blockIdx.x * 64;
    int n0 = blockIdx.y * 128;

    const float* y = (const float*)g_y;

    int arow = tid >> 2;             // 0..63
    int ak   = (tid & 3) * 4;        // 0,4,8,12
    int brow = tid >> 4;             // 0..15
    int bc   = (tid & 15) * 8;       // 0..120

    float d[2][4][4];
#pragma unroll
    for (int t = 0; t < 2; t++)
#pragma unroll
        for (int u = 0; u < 4; u++)
#pragma unroll
            for (int i = 0; i < 4; i++) d[t][u][i] = 0.f;

    for (int k0 = 0; k0 < F_DIM; k0 += 16) {
        {
            int gm = m0 + arow;
            float4 av = make_float4(0.f, 0.f, 0.f, 0.f);
            if (gm < N_NODES) av = *(const float4*)&y[gm * F_DIM + k0 + ak];
            As[ak + 0][arow] = tf32_rna(av.x);
            As[ak + 1][arow] = tf32_rna(av.y);
            As[ak + 2][arow] = tf32_rna(av.z);
            As[ak + 3][arow] = tf32_rna(av.w);
        }
        {
            const float* wrow = &W1[(k0 + brow) * HID + n0 + bc];
            float4 bv0 = *(const float4*)&wrow[0];
            float4 bv1 = *(const float4*)&wrow[4];
            Bs[brow][bc + 0] = tf32_rna(bv0.x);
            Bs[brow][bc + 1] = tf32_rna(bv0.y);
            Bs[brow][bc + 2] = tf32_rna(bv0.z);
            Bs[brow][bc + 3] = tf32_rna(bv0.w);
            Bs[brow][bc + 4] = tf32_rna(bv1.x);
            Bs[brow][bc + 5] = tf32_rna(bv1.y);
            Bs[brow][bc + 6] = tf32_rna(bv1.z);
            Bs[brow][bc + 7] = tf32_rna(bv1.w);
        }
        __syncthreads();

#pragma unroll
        for (int k8 = 0; k8 < 16; k8 += 8) {
            unsigned a[2][4], b[4][2];
            int kA = k8 + qcol;
#pragma unroll
            for (int t = 0; t < 2; t++) {
                int mr = warp_m * 32 + t * 16 + qrow;
                a[t][0] = __float_as_uint(As[kA][mr]);
                a[t][1] = __float_as_uint(As[kA][mr + 8]);
                a[t][2] = __float_as_uint(As[kA + 4][mr]);
                a[t][3] = __float_as_uint(As[kA + 4][mr + 8]);
            }
#pragma unroll
            for (int u = 0; u < 4; u++) {
                int bcol = warp_n * 32 + u * 8 + qrow;
                b[u][0] = __float_as_uint(Bs[kA][bcol]);
                b[u][1] = __float_as_uint(Bs[kA + 4][bcol]);
            }
#pragma unroll
            for (int t = 0; t < 2; t++)
#pragma unroll
                for (int u = 0; u < 4; u++)
                    MMA_TF32(d[t][u], a[t], b[u]);
        }
        __syncthreads();
    }

    float* h = (float*)g_h;
#pragma unroll
    for (int t = 0; t < 2; t++) {
        int r0 = m0 + warp_m * 32 + t * 16 + qrow;
#pragma unroll
        for (int u = 0; u < 4; u++) {
            int c = n0 + warp_n * 32 + u * 8 + qcol * 2;
            float2 bb = *(const float2*)&b1[c];
            if (r0 < N_NODES) {
                float2 o;
                o.x = fmaxf(d[t][u][0] + bb.x, 0.f);
                o.y = fmaxf(d[t][u][1] + bb.y, 0.f);
                *(float2*)&h[r0 * HID + c] = o;
            }
            if (r0 + 8 < N_NODES) {
                float2 o;
                o.x = fmaxf(d[t][u][2] + bb.x, 0.f);
                o.y = fmaxf(d[t][u][3] + bb.y, 0.f);
                *(float2*)&h[(r0 + 8) * HID + c] = o;
            }
        }
    }
}

// ---------------- GEMM2 (tf32 MMA) + fused log_softmax --------------------------
// BM=128, N=40 (5 n-tiles), K chunked by 32; 256 threads = 8 warps, warp owns 16 rows
__global__ __launch_bounds__(256) void gemm2_kernel(const float* __restrict__ W2,
                                                    const float* __restrict__ b2,
                                                    float* __restrict__ out) {
    __shared__ float hs[32][132];   // [k][m] tf32
    __shared__ float ws[32][44];    // [k][n] tf32
    __shared__ float lg[128][41];   // logits

    int tid  = threadIdx.x;
    int lane = tid & 31;
    int wid  = tid >> 5;            // warp owns rows wid*16 .. +15
    int qrow = lane >> 2;
    int qcol = lane & 3;
    int m0 = blockIdx.x * 128;

    const float* h = (const float*)g_h;

    float d[5][4];
#pragma unroll
    for (int u = 0; u < 5; u++)
#pragma unroll
        for (int i = 0; i < 4; i++) d[u][i] = 0.f;

    int arow = tid >> 1;            // 0..127
    int ak   = (tid & 1) * 16;      // 0 or 16

    for (int k0 = 0; k0 < HID; k0 += 32) {
        // stage h chunk (128 rows x 32 k): 4 float4 per thread
        {
            int gm = m0 + arow;
            const float* hp = &h[gm * HID + k0 + ak];
#pragma unroll
            for (int q = 0; q < 4; q++) {
                float4 v = make_float4(0.f, 0.f, 0.f, 0.f);
                if (gm < N_NODES) v = *(const float4*)&hp[q * 4];
                hs[ak + q * 4 + 0][arow] = tf32_rna(v.x);
                hs[ak + q * 4 + 1][arow] = tf32_rna(v.y);
                hs[ak + q * 4 + 2][arow] = tf32_rna(v.z);
                hs[ak + q * 4 + 3][arow] = tf32_rna(v.w);
            }
        }
        // stage W2 chunk (32 k x 40 n)
        for (int idx = tid; idx < 32 * NCLS; idx += 256) {
            int kk = idx / NCLS, cc = idx - kk * NCLS;
            ws[kk][cc] = tf32_rna(W2[(k0 + kk) * NCLS + cc]);
        }
        __syncthreads();

#pragma unroll
        for (int k8 = 0; k8 < 32; k8 += 8) {
            int kA = k8 + qcol;
            int mr = wid * 16 + qrow;
            unsigned a[4];
            a[0] = __float_as_uint(hs[kA][mr]);
            a[1] = __float_as_uint(hs[kA][mr + 8]);
            a[2] = __float_as_uint(hs[kA + 4][mr]);
            a[3] = __float_as_uint(hs[kA + 4][mr + 8]);
#pragma unroll
            for (int u = 0; u < 5; u++) {
                unsigned b[2];
                b[0] = __float_as_uint(ws[kA][u * 8 + qrow]);
                b[1] = __float_as_uint(ws[kA + 4][u * 8 + qrow]);
                MMA_TF32(d[u], a, b);
            }
        }
        __syncthreads();
    }

    // logits + bias into smem
    {
        int mr = wid * 16 + qrow;
#pragma unroll
        for (int u = 0; u < 5; u++) {
            int c = u * 8 + qcol * 2;
            float2 bb = *(const float2*)&b2[c];
            lg[mr][c]         = d[u][0] + bb.x;
            lg[mr][c + 1]     = d[u][1] + bb.y;
            lg[mr + 8][c]     = d[u][2] + bb.x;
            lg[mr + 8][c + 1] = d[u][3] + bb.y;
        }
    }
    __syncthreads();

    // log_softmax: one thread per row
    if (tid < 128) {
        int row = m0 + tid;
        if (row < N_NODES) {
            float m = -1e30f;
#pragma unroll
            for (int c = 0; c < NCLS; c++) m = fmaxf(m, lg[tid][c]);
            float s = 0.f;
#pragma unroll
            for (int c = 0; c < NCLS; c++) s += expf(lg[tid][c] - m);
            float sub = m + logf(s);
            float* orow = &out[row * NCLS];
#pragma unroll
            for (int c = 0; c < NCLS; c++) orow[c] = lg[tid][c] - sub;
        }
    }
}

// ---------------- launch ----------------
extern "C" void kernel_launch(void* const* d_in, const int* in_sizes, int n_in,
                              void* d_out, int out_size) {
    const float* features = (const float*)d_in[0];
    const int*   src      = (const int*)d_in[1];
    const int*   dst      = (const int*)d_in[2];
    const float* W1       = (const float*)d_in[3];
    const float* b1       = (const float*)d_in[4];
    const float* W2       = (const float*)d_in[5];
    const float* b2       = (const float*)d_in[6];
    float*       out      = (float*)d_out;

    const int NB  = (N_NODES + 255) / 256;      // 196
    const int EB  = (N_EDGES + 255) / 256;      // 3125
    const int PB  = (N_NODES + 7) / 8;          // 6250
    const float4* feat4 = (const float4*)features;

    zero_deg_kernel<<<NB, 256>>>();                               // 1
    deg_kernel<<<EB, 256>>>(dst);                                 // 2
    scan1_kernel<<<SCAN_BLOCKS, 256>>>();                         // 3
    scan3_kernel<<<SCAN_BLOCKS, 256>>>(feat4);                    // 4 (+fp16 init)
    fill_kernel<<<EB, 256>>>(src, dst);                           // 5

    prop_kernel<0><<<PB, 256>>>(0, feat4);   // 6  <- profiled by ncu -s 5 -c 1
    prop_kernel<1><<<PB, 256>>>(1, feat4);   // 7
    prop_kernel<2><<<PB, 256>>>(0, feat4);   // 8

    dim3 g1((N_NODES + 63) / 64, HID / 128);    // (782, 2)
    gemm1_kernel<<<g1, 256>>>(W1, b1);          // 9

    const int G2B = (N_NODES + 127) / 128;      // 391
    gemm2_kernel<<<G2B, 256>>>(W2, b2, out);    // 10
}

// round 12
// speedup vs baseline: 2.0579x; 1.1543x over previous
#include <cuda_runtime.h>
#include <cuda_fp16.h>
#include <math.h>

#define N_NODES 50000
#define N_EDGES 800000
#define F_DIM   128
#define F4      32      // float4 per feature row
#define HID     256
#define NCLS    40

#define SCAN_BLOCKS ((N_NODES + 255) / 256)   // 196

// ---------------- device scratch (static: no allocation allowed) ----------------
// RULE (learned R3-R5): never pass __device__ symbol addresses from host code —
// on GB300 the host-side shadow resolves via ATS to HOST memory. All buffer
// selection happens inside device code.
__device__ int    g_deg[N_NODES];
__device__ int    g_rowstart[N_NODES + 1];
__device__ int    g_cursor[N_NODES];
__device__ int    g_bsum[SCAN_BLOCKS];
__device__ float  g_norm[N_NODES];
__device__ int2   g_csr[N_EDGES];           // (src, norm[src] as bits)
__device__ __half g_xh0[N_NODES * F_DIM];   // fp16 ping
__device__ __half g_xh1[N_NODES * F_DIM];   // fp16 pong; holds final fp16 y
__device__ float4 g_y [N_NODES * F4];       // fp32 running sum
__device__ __half g_h [N_NODES * HID];      // fp16 hidden activations

// ---------------- build: degree ----------------
__global__ void zero_deg_kernel() {
    int i = blockIdx.x * blockDim.x + threadIdx.x;
    if (i < N_NODES) g_deg[i] = 0;
}

__global__ void deg_kernel(const int* __restrict__ dst) {
    int i = blockIdx.x * blockDim.x + threadIdx.x;
    if (i < N_EDGES) atomicAdd(&g_deg[dst[i]], 1);
}

// ---------------- hierarchical scan ----------------
__device__ __forceinline__ int warp_incl_scan(int v, int lane) {
#pragma unroll
    for (int o = 1; o < 32; o <<= 1) {
        int n = __shfl_up_sync(0xffffffffu, v, o);
        if (lane >= o) v += n;
    }
    return v;
}

__device__ __forceinline__ int block_incl_scan_256(int v, int tid) {
    __shared__ int ws[8];
    int lane = tid & 31, w = tid >> 5;
    int incl = warp_incl_scan(v, lane);
    if (lane == 31) ws[w] = incl;
    __syncthreads();
    if (w == 0) {
        int s = (lane < 8) ? ws[lane] : 0;
        s = warp_incl_scan(s, lane);
        if (lane < 8) ws[lane] = s;
    }
    __syncthreads();
    if (w > 0) incl += ws[w - 1];
    return incl;
}

__global__ void scan1_kernel() {
    int tid = threadIdx.x;
    int i = blockIdx.x * 256 + tid;
    int v = (i < N_NODES) ? g_deg[i] : 0;
    if (i < N_NODES) g_norm[i] = rsqrtf((float)(v < 1 ? 1 : v));
    int incl = block_incl_scan_256(v, tid);
    if (i < N_NODES) g_rowstart[i] = incl - v;
    if (tid == 255) g_bsum[blockIdx.x] = incl;
}

// phase 2 (merged): bsum prefix per block, add offsets; ALSO convert this
// block's feature slice into fp16 g_xh0 (init fused in)
__global__ void scan3_kernel(const float4* __restrict__ feat) {
    __shared__ int ssum[8];
    int tid = threadIdx.x;
    int bid = blockIdx.x;
    int lane = tid & 31, w = tid >> 5;

    int v = (tid < bid && tid < SCAN_BLOCKS) ? g_bsum[tid] : 0;
#pragma unroll
    for (int o = 16; o > 0; o >>= 1) v += __shfl_down_sync(0xffffffffu, v, o);
    if (lane == 0) ssum[w] = v;
    __syncthreads();
    if (tid == 0) {
        int s = 0;
#pragma unroll
        for (int i = 0; i < 8; i++) s += ssum[i];
        ssum[0] = s;
    }
    __syncthreads();
    int off = ssum[0];

    int i = bid * 256 + tid;
    if (i < N_NODES) {
        int r = g_rowstart[i] + off;
        g_rowstart[i] = r;
        g_cursor[i]   = r;
    }
    if (i == 0) g_rowstart[N_NODES] = N_EDGES;

    uint2* xh0v = (uint2*)g_xh0;
    int base = bid * 256 * F4;
    int lim  = N_NODES * F4 - base;
    int n    = 256 * F4 < lim ? 256 * F4 : lim;
    for (int j = tid; j < n; j += 256) {
        float4 f = feat[base + j];
        __half2 h0 = __floats2half2_rn(f.x, f.y);
        __half2 h1 = __floats2half2_rn(f.z, f.w);
        uint2 u;
        u.x = *(unsigned*)&h0;
        u.y = *(unsigned*)&h1;
        xh0v[base + j] = u;
    }
}

// fill CSR: (src, norm[src]) interleaved
__global__ void fill_kernel(const int* __restrict__ src, const int* __restrict__ dst) {
    int i = blockIdx.x * blockDim.x + threadIdx.x;
    if (i < N_EDGES) {
        int s = src[i];
        int d = dst[i];
        int pos = atomicAdd(&g_cursor[d], 1);
        int2 v;
        v.x = s;
        v.y = __float_as_int(g_norm[s]);
        g_csr[pos] = v;
    }
}

// ---------------- propagation: pull over fp16 CSR gather, fp32 accumulate -------
// MODE 0: y = feat + acc ; MODE 1: y += acc ; MODE 2: y=(y+acc)/4 -> fp16 xout
__device__ __forceinline__ void gacc(uint2 u, float w, float4& acc) {
    float2 f0 = __half22float2(*(__half2*)&u.x);
    float2 f1 = __half22float2(*(__half2*)&u.y);
    acc.x = fmaf(f0.x, w, acc.x);
    acc.y = fmaf(f0.y, w, acc.y);
    acc.z = fmaf(f1.x, w, acc.z);
    acc.w = fmaf(f1.y, w, acc.w);
}

template<int MODE>
__global__ void prop_kernel(int dir, const float4* __restrict__ feat) {
    const __half* __restrict__ xin  = dir ? g_xh1 : g_xh0;
    __half*       __restrict__ xout = dir ? g_xh0 : g_xh1;

    int node = blockIdx.x * 8 + (threadIdx.x >> 5);
    int lane = threadIdx.x & 31;
    if (node >= N_NODES) return;

    int beg = g_rowstart[node];
    int end = g_rowstart[node + 1];
    int lane4 = lane * 4;

    float4 acc = make_float4(0.f, 0.f, 0.f, 0.f);
    int e = beg;
    for (; e + 4 <= end; e += 4) {
        int2 c0 = __ldg(&g_csr[e + 0]);
        int2 c1 = __ldg(&g_csr[e + 1]);
        int2 c2 = __ldg(&g_csr[e + 2]);
        int2 c3 = __ldg(&g_csr[e + 3]);
        uint2 u0 = __ldg((const uint2*)(xin + c0.x * F_DIM + lane4));
        uint2 u1 = __ldg((const uint2*)(xin + c1.x * F_DIM + lane4));
        uint2 u2 = __ldg((const uint2*)(xin + c2.x * F_DIM + lane4));
        uint2 u3 = __ldg((const uint2*)(xin + c3.x * F_DIM + lane4));
        gacc(u0, __int_as_float(c0.y), acc);
        gacc(u1, __int_as_float(c1.y), acc);
        gacc(u2, __int_as_float(c2.y), acc);
        gacc(u3, __int_as_float(c3.y), acc);
    }
    for (; e < end; e++) {
        int2 c = __ldg(&g_csr[e]);
        uint2 u = __ldg((const uint2*)(xin + c.x * F_DIM + lane4));
        gacc(u, __int_as_float(c.y), acc);
    }

    float nd = g_norm[node];
    acc.x *= nd; acc.y *= nd; acc.z *= nd; acc.w *= nd;

    int idx = node * F4 + lane;
    if (MODE == 0) {
        __half2 o0 = __floats2half2_rn(acc.x, acc.y);
        __half2 o1 = __floats2half2_rn(acc.z, acc.w);
        uint2 u;
        u.x = *(unsigned*)&o0;
        u.y = *(unsigned*)&o1;
        *(uint2*)(xout + node * F_DIM + lane4) = u;

        float4 f = __ldg(&feat[idx]);
        f.x += acc.x; f.y += acc.y; f.z += acc.z; f.w += acc.w;
        g_y[idx] = f;
    } else if (MODE == 1) {
        __half2 o0 = __floats2half2_rn(acc.x, acc.y);
        __half2 o1 = __floats2half2_rn(acc.z, acc.w);
        uint2 u;
        u.x = *(unsigned*)&o0;
        u.y = *(unsigned*)&o1;
        *(uint2*)(xout + node * F_DIM + lane4) = u;

        float4 yv = g_y[idx];
        yv.x += acc.x; yv.y += acc.y; yv.z += acc.z; yv.w += acc.w;
        g_y[idx] = yv;
    } else {
        float4 yv = g_y[idx];
        yv.x = (yv.x + acc.x) * 0.25f;
        yv.y = (yv.y + acc.y) * 0.25f;
        yv.z = (yv.z + acc.z) * 0.25f;
        yv.w = (yv.w + acc.w) * 0.25f;
        // final feat matrix, pre-scaled, as fp16 into xout (g_xh1 when dir=0)
        __half2 o0 = __floats2half2_rn(yv.x, yv.y);
        __half2 o1 = __floats2half2_rn(yv.z, yv.w);
        uint2 u;
        u.x = *(unsigned*)&o0;
        u.y = *(unsigned*)&o1;
        *(uint2*)(xout + node * F_DIM + lane4) = u;
    }
}

// ---------------- fp16 MMA helper -----------------------------------------------
#define MMA_F16(D, A, B) \
    asm volatile("mma.sync.aligned.m16n8k16.row.col.f32.f16.f16.f32 " \
        "{%0,%1,%2,%3}, {%4,%5,%6,%7}, {%8,%9}, {%0,%1,%2,%3};" \
        : "+f"((D)[0]), "+f"((D)[1]), "+f"((D)[2]), "+f"((D)[3]) \
        : "r"((A)[0]), "r"((A)[1]), "r"((A)[2]), "r"((A)[3]), \
          "r"((B)[0]), "r"((B)[1]))

// ---------------- GEMM1 (fp16 MMA): h = relu( y16 @ W1 + b1 ) -------------------
// BM=64, BN=128, BK=16, 256 threads = 8 warps (2m x 4n), warp tile 32x32
// A from fp16 y (g_xh1) directly; W1 converted fp32->fp16 during staging.
__global__ __launch_bounds__(256) void gemm1_kernel(const float* __restrict__ W1,
                                                    const float* __restrict__ b1) {
    __shared__ __half2 As2[8][68];    // [k2][m]  (k,k+1) pairs
    __shared__ __half2 Bs2[8][132];   // [k2][n]

    int tid  = threadIdx.x;
    int lane = tid & 31;
    int wid  = tid >> 5;
    int warp_m = wid & 1;
    int warp_n = wid >> 1;
    int qrow = lane >> 2;
    int qcol = lane & 3;

    int m0 = blockIdx.x * 64;
    int n0 = blockIdx.y * 128;

    int arow = tid >> 2;             // 0..63
    int ak   = (tid & 3) * 4;        // halves 0,4,8,12

    float d[2][4][4];
#pragma unroll
    for (int t = 0; t < 2; t++)
#pragma unroll
        for (int u = 0; u < 4; u++)
#pragma unroll
            for (int i = 0; i < 4; i++) d[t][u][i] = 0.f;

    for (int k0 = 0; k0 < F_DIM; k0 += 16) {
        // stage A (64 x 16 halves): 1 uint2 per thread, no conversion
        {
            int gm = m0 + arow;
            uint2 u = make_uint2(0u, 0u);
            if (gm < N_NODES) u = *(const uint2*)(g_xh1 + gm * F_DIM + k0 + ak);
            As2[(ak >> 1)    ][arow] = *(__half2*)&u.x;
            As2[(ak >> 1) + 1][arow] = *(__half2*)&u.y;
        }
        // stage B (16 k x 128 n): 4 half2 per thread, cvt from fp32 W1
#pragma unroll
        for (int q = 0; q < 4; q++) {
            int idx = tid + 256 * q;          // 0..1023
            int p = idx >> 7;                 // k-pair 0..7
            int n = idx & 127;
            float w0 = W1[(k0 + 2 * p)     * HID + n0 + n];
            float w1 = W1[(k0 + 2 * p + 1) * HID + n0 + n];
            Bs2[p][n] = __floats2half2_rn(w0, w1);
        }
        __syncthreads();

        {
            unsigned a[2][4], b[4][2];
#pragma unroll
            for (int t = 0; t < 2; t++) {
                int mr = warp_m * 32 + t * 16 + qrow;
                a[t][0] = *(unsigned*)&As2[qcol][mr];
                a[t][1] = *(unsigned*)&As2[qcol][mr + 8];
                a[t][2] = *(unsigned*)&As2[qcol + 4][mr];
                a[t][3] = *(unsigned*)&As2[qcol + 4][mr + 8];
            }
#pragma unroll
            for (int u = 0; u < 4; u++) {
                int bcol = warp_n * 32 + u * 8 + qrow;
                b[u][0] = *(unsigned*)&Bs2[qcol][bcol];
                b[u][1] = *(unsigned*)&Bs2[qcol + 4][bcol];
            }
#pragma unroll
            for (int t = 0; t < 2; t++)
#pragma unroll
                for (int u = 0; u < 4; u++)
                    MMA_F16(d[t][u], a[t], b[u]);
        }
        __syncthreads();
    }

    // epilogue: bias + relu, store fp16 h
#pragma unroll
    for (int t = 0; t < 2; t++) {
        int r0 = m0 + warp_m * 32 + t * 16 + qrow;
#pragma unroll
        for (int u = 0; u < 4; u++) {
            int c = n0 + warp_n * 32 + u * 8 + qcol * 2;
            float2 bb = *(const float2*)&b1[c];
            if (r0 < N_NODES) {
                __half2 o = __floats2half2_rn(fmaxf(d[t][u][0] + bb.x, 0.f),
                                              fmaxf(d[t][u][1] + bb.y, 0.f));
                *(__half2*)(g_h + r0 * HID + c) = o;
            }
            if (r0 + 8 < N_NODES) {
                __half2 o = __floats2half2_rn(fmaxf(d[t][u][2] + bb.x, 0.f),
                                              fmaxf(d[t][u][3] + bb.y, 0.f));
                *(__half2*)(g_h + (r0 + 8) * HID + c) = o;
            }
        }
    }
}

// ---------------- GEMM2 (fp16 MMA) + fused log_softmax --------------------------
// BM=128, N=40 (5 n-tiles), K chunked by 32; 256 threads = 8 warps, warp = 16 rows
__global__ __launch_bounds__(256) void gemm2_kernel(const float* __restrict__ W2,
                                                    const float* __restrict__ b2,
                                                    float* __restrict__ out) {
    __shared__ __half2 hs2[16][132];  // [k2][m]
    __shared__ __half2 ws2[16][44];   // [k2][n]
    __shared__ float   lg[128][41];   // logits

    int tid  = threadIdx.x;
    int lane = tid & 31;
    int wid  = tid >> 5;
    int qrow = lane >> 2;
    int qcol = lane & 3;
    int m0 = blockIdx.x * 128;

    float d[5][4];
#pragma unroll
    for (int u = 0; u < 5; u++)
#pragma unroll
        for (int i = 0; i < 4; i++) d[u][i] = 0.f;

    int arow = tid >> 1;            // 0..127
    int ak   = (tid & 1) * 16;      // halves 0 or 16

    for (int k0 = 0; k0 < HID; k0 += 32) {
        // stage h chunk (128 rows x 32 halves): 2 uint4 per thread, no cvt
        {
            int gm = m0 + arow;
            const __half* hp = g_h + gm * HID + k0 + ak;
            uint4 v0 = make_uint4(0u, 0u, 0u, 0u), v1 = v0;
            if (gm < N_NODES) {
                v0 = *(const uint4*)hp;
                v1 = *(const uint4*)(hp + 8);
            }
            int k2b = ak >> 1;        // 0 or 8
            hs2[k2b + 0][arow] = *(__half2*)&v0.x;
            hs2[k2b + 1][arow] = *(__half2*)&v0.y;
            hs2[k2b + 2][arow] = *(__half2*)&v0.z;
            hs2[k2b + 3][arow] = *(__half2*)&v0.w;
            hs2[k2b + 4][arow] = *(__half2*)&v1.x;
            hs2[k2b + 5][arow] = *(__half2*)&v1.y;
            hs2[k2b + 6][arow] = *(__half2*)&v1.z;
            hs2[k2b + 7][arow] = *(__half2*)&v1.w;
        }
        // stage W2 chunk (32 k x 40 n): 640 half2
        for (int idx = tid; idx < 16 * NCLS; idx += 256) {
            int p = idx / NCLS, n = idx - p * NCLS;
            float w0 = W2[(k0 + 2 * p)     * NCLS + n];
            float w1 = W2[(k0 + 2 * p + 1) * NCLS + n];
            ws2[p][n] = __floats2half2_rn(w0, w1);
        }
        __syncthreads();

#pragma unroll
        for (int ks = 0; ks < 2; ks++) {
            int kA = ks * 8 + qcol;
            int mr = wid * 16 + qrow;
            unsigned a[4];
            a[0] = *(unsigned*)&hs2[kA][mr];
            a[1] = *(unsigned*)&hs2[kA][mr + 8];
            a[2] = *(unsigned*)&hs2[kA + 4][mr];
            a[3] = *(unsigned*)&hs2[kA + 4][mr + 8];
#pragma unroll
            for (int u = 0; u < 5; u++) {
                unsigned b[2];
                b[0] = *(unsigned*)&ws2[kA][u * 8 + qrow];
                b[1] = *(unsigned*)&ws2[kA + 4][u * 8 + qrow];
                MMA_F16(d[u], a, b);
            }
        }
        __syncthreads();
    }

    // logits + bias into smem
    {
        int mr = wid * 16 + qrow;
#pragma unroll
        for (int u = 0; u < 5; u++) {
            int c = u * 8 + qcol * 2;
            float2 bb = *(const float2*)&b2[c];
            lg[mr][c]         = d[u][0] + bb.x;
            lg[mr][c + 1]     = d[u][1] + bb.y;
            lg[mr + 8][c]     = d[u][2] + bb.x;
            lg[mr + 8][c + 1] = d[u][3] + bb.y;
        }
    }
    __syncthreads();

    // log_softmax: one thread per row
    if (tid < 128) {
        int row = m0 + tid;
        if (row < N_NODES) {
            float m = -1e30f;
#pragma unroll
            for (int c = 0; c < NCLS; c++) m = fmaxf(m, lg[tid][c]);
            float s = 0.f;
#pragma unroll
            for (int c = 0; c < NCLS; c++) s += expf(lg[tid][c] - m);
            float sub = m + logf(s);
            float* orow = &out[row * NCLS];
#pragma unroll
            for (int c = 0; c < NCLS; c++) orow[c] = lg[tid][c] - sub;
        }
    }
}

// ---------------- launch ----------------
extern "C" void kernel_launch(void* const* d_in, const int* in_sizes, int n_in,
                              void* d_out, int out_size) {
    const float* features = (const float*)d_in[0];
    const int*   src      = (const int*)d_in[1];
    const int*   dst      = (const int*)d_in[2];
    const float* W1       = (const float*)d_in[3];
    const float* b1       = (const float*)d_in[4];
    const float* W2       = (const float*)d_in[5];
    const float* b2       = (const float*)d_in[6];
    float*       out      = (float*)d_out;

    const int NB  = (N_NODES + 255) / 256;      // 196
    const int EB  = (N_EDGES + 255) / 256;      // 3125
    const int PB  = (N_NODES + 7) / 8;          // 6250
    const float4* feat4 = (const float4*)features;

    zero_deg_kernel<<<NB, 256>>>();                               // 1
    deg_kernel<<<EB, 256>>>(dst);                                 // 2
    scan1_kernel<<<SCAN_BLOCKS, 256>>>();                         // 3
    scan3_kernel<<<SCAN_BLOCKS, 256>>>(feat4);                    // 4 (+fp16 init)
    fill_kernel<<<EB, 256>>>(src, dst);                           // 5

    prop_kernel<0><<<PB, 256>>>(0, feat4);   // 6  <- profiled by ncu -s 5 -c 1
    prop_kernel<1><<<PB, 256>>>(1, feat4);   // 7
    prop_kernel<2><<<PB, 256>>>(0, feat4);   // 8 (writes fp16 y into g_xh1)

    dim3 g1((N_NODES + 63) / 64, HID / 128);    // (782, 2)
    gemm1_kernel<<<g1, 256>>>(W1, b1);          // 9

    const int G2B = (N_NODES + 127) / 128;      // 391
    gemm2_kernel<<<G2B, 256>>>(W2, b2, out);    // 10
}

// round 13
// speedup vs baseline: 2.1853x; 1.0619x over previous
#include <cuda_runtime.h>
#include <cuda_fp16.h>
#include <math.h>

#define N_NODES 50000
#define N_EDGES 800000
#define F_DIM   128
#define F4      32      // float4 per feature row
#define HID     256
#define NCLS    40

#define SCAN_BLOCKS ((N_NODES + 255) / 256)   // 196

// ---------------- device scratch (static: no allocation allowed) ----------------
// RULE (learned R3-R5): never pass __device__ symbol addresses from host code —
// on GB300 the host-side shadow resolves via ATS to HOST memory. All buffer
// selection happens inside device code.
__device__ int    g_deg[N_NODES];
__device__ int    g_rowstart[N_NODES + 1];
__device__ int    g_cursor[N_NODES];
__device__ int    g_bsum[SCAN_BLOCKS];
__device__ float  g_norm[N_NODES];
__device__ int2   g_csr[N_EDGES];           // (src, norm[src] as bits)
__device__ __half g_xh0[N_NODES * F_DIM];   // fp16 ping
__device__ __half g_xh1[N_NODES * F_DIM];   // fp16 pong; holds final fp16 y
__device__ __half g_yh [N_NODES * F_DIM];   // fp16 running sum (fp32 math)
__device__ __half g_h  [N_NODES * HID];     // fp16 hidden activations

// ---------------- build: degree ----------------
__global__ void zero_deg_kernel() {
    int i = blockIdx.x * blockDim.x + threadIdx.x;
    if (i < N_NODES) g_deg[i] = 0;
}

__global__ void deg_kernel(const int4* __restrict__ dst4) {
    int i = blockIdx.x * blockDim.x + threadIdx.x;
    if (i < N_EDGES / 4) {
        int4 d = dst4[i];
        atomicAdd(&g_deg[d.x], 1);
        atomicAdd(&g_deg[d.y], 1);
        atomicAdd(&g_deg[d.z], 1);
        atomicAdd(&g_deg[d.w], 1);
    }
}

// ---------------- hierarchical scan ----------------
__device__ __forceinline__ int warp_incl_scan(int v, int lane) {
#pragma unroll
    for (int o = 1; o < 32; o <<= 1) {
        int n = __shfl_up_sync(0xffffffffu, v, o);
        if (lane >= o) v += n;
    }
    return v;
}

__device__ __forceinline__ int block_incl_scan_256(int v, int tid) {
    __shared__ int ws[8];
    int lane = tid & 31, w = tid >> 5;
    int incl = warp_incl_scan(v, lane);
    if (lane == 31) ws[w] = incl;
    __syncthreads();
    if (w == 0) {
        int s = (lane < 8) ? ws[lane] : 0;
        s = warp_incl_scan(s, lane);
        if (lane < 8) ws[lane] = s;
    }
    __syncthreads();
    if (w > 0) incl += ws[w - 1];
    return incl;
}

__global__ void scan1_kernel() {
    int tid = threadIdx.x;
    int i = blockIdx.x * 256 + tid;
    int v = (i < N_NODES) ? g_deg[i] : 0;
    if (i < N_NODES) g_norm[i] = rsqrtf((float)(v < 1 ? 1 : v));
    int incl = block_incl_scan_256(v, tid);
    if (i < N_NODES) g_rowstart[i] = incl - v;
    if (tid == 255) g_bsum[blockIdx.x] = incl;
}

// phase 2: blocks < SCAN_BLOCKS do offset fixup; ALL blocks (4x grid) convert
// the feature matrix to fp16 via grid-stride (higher copy occupancy)
__global__ void scan3_kernel(const float4* __restrict__ feat) {
    __shared__ int ssum[8];
    int tid = threadIdx.x;
    int bid = blockIdx.x;
    int lane = tid & 31, w = tid >> 5;

    if (bid < SCAN_BLOCKS) {
        int v = (tid < bid && tid < SCAN_BLOCKS) ? g_bsum[tid] : 0;
#pragma unroll
        for (int o = 16; o > 0; o >>= 1) v += __shfl_down_sync(0xffffffffu, v, o);
        if (lane == 0) ssum[w] = v;
        __syncthreads();
        if (tid == 0) {
            int s = 0;
#pragma unroll
            for (int i = 0; i < 8; i++) s += ssum[i];
            ssum[0] = s;
        }
        __syncthreads();
        int off = ssum[0];

        int i = bid * 256 + tid;
        if (i < N_NODES) {
            int r = g_rowstart[i] + off;
            g_rowstart[i] = r;
            g_cursor[i]   = r;
        }
        if (i == 0) g_rowstart[N_NODES] = N_EDGES;
    }

    // grid-stride fp16 conversion of features (all blocks)
    uint2* xh0v = (uint2*)g_xh0;
    int stride = gridDim.x * 256;
    for (int j = bid * 256 + tid; j < N_NODES * F4; j += stride) {
        float4 f = feat[j];
        __half2 h0 = __floats2half2_rn(f.x, f.y);
        __half2 h1 = __floats2half2_rn(f.z, f.w);
        uint2 u;
        u.x = *(unsigned*)&h0;
        u.y = *(unsigned*)&h1;
        xh0v[j] = u;
    }
}

// fill CSR: (src, norm[src]) interleaved, int4 edge loads
__global__ void fill_kernel(const int4* __restrict__ src4, const int4* __restrict__ dst4) {
    int i = blockIdx.x * blockDim.x + threadIdx.x;
    if (i < N_EDGES / 4) {
        int4 s = src4[i];
        int4 d = dst4[i];
        int2 v;
        int pos;
        pos = atomicAdd(&g_cursor[d.x], 1);
        v.x = s.x; v.y = __float_as_int(g_norm[s.x]); g_csr[pos] = v;
        pos = atomicAdd(&g_cursor[d.y], 1);
        v.x = s.y; v.y = __float_as_int(g_norm[s.y]); g_csr[pos] = v;
        pos = atomicAdd(&g_cursor[d.z], 1);
        v.x = s.z; v.y = __float_as_int(g_norm[s.z]); g_csr[pos] = v;
        pos = atomicAdd(&g_cursor[d.w], 1);
        v.x = s.w; v.y = __float_as_int(g_norm[s.w]); g_csr[pos] = v;
    }
}

// ---------------- propagation: pull over fp16 CSR gather, fp32 accumulate -------
// MODE 0: y16 = xin16[node] + acc ; MODE 1: y16 += acc ;
// MODE 2: y_final = (y16 + acc)*0.25 -> fp16 into xout (g_xh1); no y write
__device__ __forceinline__ void gacc(uint2 u, float w, float4& acc) {
    float2 f0 = __half22float2(*(__half2*)&u.x);
    float2 f1 = __half22float2(*(__half2*)&u.y);
    acc.x = fmaf(f0.x, w, acc.x);
    acc.y = fmaf(f0.y, w, acc.y);
    acc.z = fmaf(f1.x, w, acc.z);
    acc.w = fmaf(f1.y, w, acc.w);
}

__device__ __forceinline__ uint2 pack_h4(float4 v) {
    __half2 o0 = __floats2half2_rn(v.x, v.y);
    __half2 o1 = __floats2half2_rn(v.z, v.w);
    uint2 u;
    u.x = *(unsigned*)&o0;
    u.y = *(unsigned*)&o1;
    return u;
}

__device__ __forceinline__ float4 unpack_h4(uint2 u) {
    float2 f0 = __half22float2(*(__half2*)&u.x);
    float2 f1 = __half22float2(*(__half2*)&u.y);
    return make_float4(f0.x, f0.y, f1.x, f1.y);
}

template<int MODE>
__global__ void prop_kernel(int dir) {
    const __half* __restrict__ xin  = dir ? g_xh1 : g_xh0;
    __half*       __restrict__ xout = dir ? g_xh0 : g_xh1;

    int node = blockIdx.x * 8 + (threadIdx.x >> 5);
    int lane = threadIdx.x & 31;
    if (node >= N_NODES) return;

    int beg = g_rowstart[node];
    int end = g_rowstart[node + 1];
    int lane4 = lane * 4;

    float4 acc = make_float4(0.f, 0.f, 0.f, 0.f);
    int e = beg;
    for (; e + 4 <= end; e += 4) {
        int2 c0 = __ldg(&g_csr[e + 0]);
        int2 c1 = __ldg(&g_csr[e + 1]);
        int2 c2 = __ldg(&g_csr[e + 2]);
        int2 c3 = __ldg(&g_csr[e + 3]);
        uint2 u0 = __ldg((const uint2*)(xin + c0.x * F_DIM + lane4));
        uint2 u1 = __ldg((const uint2*)(xin + c1.x * F_DIM + lane4));
        uint2 u2 = __ldg((const uint2*)(xin + c2.x * F_DIM + lane4));
        uint2 u3 = __ldg((const uint2*)(xin + c3.x * F_DIM + lane4));
        gacc(u0, __int_as_float(c0.y), acc);
        gacc(u1, __int_as_float(c1.y), acc);
        gacc(u2, __int_as_float(c2.y), acc);
        gacc(u3, __int_as_float(c3.y), acc);
    }
    for (; e < end; e++) {
        int2 c = __ldg(&g_csr[e]);
        uint2 u = __ldg((const uint2*)(xin + c.x * F_DIM + lane4));
        gacc(u, __int_as_float(c.y), acc);
    }

    float nd = g_norm[node];
    acc.x *= nd; acc.y *= nd; acc.z *= nd; acc.w *= nd;

    int hoff = node * F_DIM + lane4;
    if (MODE == 0) {
        *(uint2*)(xout + hoff) = pack_h4(acc);
        // y base = fp16 feature row (same data, L2-hot; avoids fp32 ATS re-read)
        float4 f = unpack_h4(__ldg((const uint2*)(xin + hoff)));
        f.x += acc.x; f.y += acc.y; f.z += acc.z; f.w += acc.w;
        *(uint2*)(g_yh + hoff) = pack_h4(f);
    } else if (MODE == 1) {
        *(uint2*)(xout + hoff) = pack_h4(acc);
        float4 yv = unpack_h4(*(const uint2*)(g_yh + hoff));
        yv.x += acc.x; yv.y += acc.y; yv.z += acc.z; yv.w += acc.w;
        *(uint2*)(g_yh + hoff) = pack_h4(yv);
    } else {
        float4 yv = unpack_h4(*(const uint2*)(g_yh + hoff));
        yv.x = (yv.x + acc.x) * 0.25f;
        yv.y = (yv.y + acc.y) * 0.25f;
        yv.z = (yv.z + acc.z) * 0.25f;
        yv.w = (yv.w + acc.w) * 0.25f;
        *(uint2*)(xout + hoff) = pack_h4(yv);   // final pre-scaled y -> g_xh1
    }
}

// ---------------- fp16 MMA helper -----------------------------------------------
#define MMA_F16(D, A, B) \
    asm volatile("mma.sync.aligned.m16n8k16.row.col.f32.f16.f16.f32 " \
        "{%0,%1,%2,%3}, {%4,%5,%6,%7}, {%8,%9}, {%0,%1,%2,%3};" \
        : "+f"((D)[0]), "+f"((D)[1]), "+f"((D)[2]), "+f"((D)[3]) \
        : "r"((A)[0]), "r"((A)[1]), "r"((A)[2]), "r"((A)[3]), \
          "r"((B)[0]), "r"((B)[1]))

// ---------------- GEMM1 (fp16 MMA): h = relu( y16 @ W1 + b1 ) -------------------
// BM=128, BN=128, BK=16, 256 threads = 8 warps (2m x 4n), warp tile 64x32
__global__ __launch_bounds__(256) void gemm1_kernel(const float* __restrict__ W1,
                                                    const float* __restrict__ b1) {
    __shared__ __half2 As2[8][132];   // [k2][m]
    __shared__ __half2 Bs2[8][132];   // [k2][n]

    int tid  = threadIdx.x;
    int lane = tid & 31;
    int wid  = tid >> 5;
    int warp_m = wid & 1;            // 0..1 -> 64 rows each
    int warp_n = wid >> 1;           // 0..3 -> 32 cols each
    int qrow = lane >> 2;
    int qcol = lane & 3;

    int m0 = blockIdx.x * 128;
    int n0 = blockIdx.y * 128;

    int arow = tid >> 1;             // 0..127
    int ak   = (tid & 1) * 8;        // halves 0 or 8

    float d[4][4][4];
#pragma unroll
    for (int t = 0; t < 4; t++)
#pragma unroll
        for (int u = 0; u < 4; u++)
#pragma unroll
            for (int i = 0; i < 4; i++) d[t][u][i] = 0.f;

    for (int k0 = 0; k0 < F_DIM; k0 += 16) {
        // stage A (128 x 16 halves): 1 uint4 (8 halves) per thread
        {
            int gm = m0 + arow;
            uint4 u = make_uint4(0u, 0u, 0u, 0u);
            if (gm < N_NODES) u = *(const uint4*)(g_xh1 + gm * F_DIM + k0 + ak);
            int p = ak >> 1;
            As2[p + 0][arow] = *(__half2*)&u.x;
            As2[p + 1][arow] = *(__half2*)&u.y;
            As2[p + 2][arow] = *(__half2*)&u.z;
            As2[p + 3][arow] = *(__half2*)&u.w;
        }
        // stage B (16 k x 128 n): 4 half2 per thread, cvt from fp32 W1
#pragma unroll
        for (int q = 0; q < 4; q++) {
            int idx = tid + 256 * q;          // 0..1023
            int p = idx >> 7;                 // k-pair 0..7
            int n = idx & 127;
            float w0 = W1[(k0 + 2 * p)     * HID + n0 + n];
            float w1 = W1[(k0 + 2 * p + 1) * HID + n0 + n];
            Bs2[p][n] = __floats2half2_rn(w0, w1);
        }
        __syncthreads();

        {
            unsigned a[4][4], b[4][2];
#pragma unroll
            for (int t = 0; t < 4; t++) {
                int mr = warp_m * 64 + t * 16 + qrow;
                a[t][0] = *(unsigned*)&As2[qcol][mr];
                a[t][1] = *(unsigned*)&As2[qcol][mr + 8];
                a[t][2] = *(unsigned*)&As2[qcol + 4][mr];
                a[t][3] = *(unsigned*)&As2[qcol + 4][mr + 8];
            }
#pragma unroll
            for (int u = 0; u < 4; u++) {
                int bcol = warp_n * 32 + u * 8 + qrow;
                b[u][0] = *(unsigned*)&Bs2[qcol][bcol];
                b[u][1] = *(unsigned*)&Bs2[qcol + 4][bcol];
            }
#pragma unroll
            for (int t = 0; t < 4; t++)
#pragma unroll
                for (int u = 0; u < 4; u++)
                    MMA_F16(d[t][u], a[t], b[u]);
        }
        __syncthreads();
    }

    // epilogue: bias + relu, store fp16 h
#pragma unroll
    for (int t = 0; t < 4; t++) {
        int r0 = m0 + warp_m * 64 + t * 16 + qrow;
#pragma unroll
        for (int u = 0; u < 4; u++) {
            int c = n0 + warp_n * 32 + u * 8 + qcol * 2;
            float2 bb = *(const float2*)&b1[c];
            if (r0 < N_NODES) {
                __half2 o = __floats2half2_rn(fmaxf(d[t][u][0] + bb.x, 0.f),
                                              fmaxf(d[t][u][1] + bb.y, 0.f));
                *(__half2*)(g_h + r0 * HID + c) = o;
            }
            if (r0 + 8 < N_NODES) {
                __half2 o = __floats2half2_rn(fmaxf(d[t][u][2] + bb.x, 0.f),
                                              fmaxf(d[t][u][3] + bb.y, 0.f));
                *(__half2*)(g_h + (r0 + 8) * HID + c) = o;
            }
        }
    }
}

// ---------------- GEMM2 (fp16 MMA) + fused log_softmax --------------------------
// BM=128, N=40 (5 n-tiles), K chunked by 32; 256 threads = 8 warps, warp = 16 rows
__global__ __launch_bounds__(256) void gemm2_kernel(const float* __restrict__ W2,
                                                    const float* __restrict__ b2,
                                                    float* __restrict__ out) {
    __shared__ __half2 hs2[16][132];  // [k2][m]
    __shared__ __half2 ws2[16][44];   // [k2][n]
    __shared__ float   lg[128][41];   // logits

    int tid  = threadIdx.x;
    int lane = tid & 31;
    int wid  = tid >> 5;
    int qrow = lane >> 2;
    int qcol = lane & 3;
    int m0 = blockIdx.x * 128;

    float d[5][4];
#pragma unroll
    for (int u = 0; u < 5; u++)
#pragma unroll
        for (int i = 0; i < 4; i++) d[u][i] = 0.f;

    int arow = tid >> 1;            // 0..127
    int ak   = (tid & 1) * 16;      // halves 0 or 16

    for (int k0 = 0; k0 < HID; k0 += 32) {
        {
            int gm = m0 + arow;
            const __half* hp = g_h + gm * HID + k0 + ak;
            uint4 v0 = make_uint4(0u, 0u, 0u, 0u), v1 = v0;
            if (gm < N_NODES) {
                v0 = *(const uint4*)hp;
                v1 = *(const uint4*)(hp + 8);
            }
            int k2b = ak >> 1;        // 0 or 8
            hs2[k2b + 0][arow] = *(__half2*)&v0.x;
            hs2[k2b + 1][arow] = *(__half2*)&v0.y;
            hs2[k2b + 2][arow] = *(__half2*)&v0.z;
            hs2[k2b + 3][arow] = *(__half2*)&v0.w;
            hs2[k2b + 4][arow] = *(__half2*)&v1.x;
            hs2[k2b + 5][arow] = *(__half2*)&v1.y;
            hs2[k2b + 6][arow] = *(__half2*)&v1.z;
            hs2[k2b + 7][arow] = *(__half2*)&v1.w;
        }
        for (int idx = tid; idx < 16 * NCLS; idx += 256) {
            int p = idx / NCLS, n = idx - p * NCLS;
            float w0 = W2[(k0 + 2 * p)     * NCLS + n];
            float w1 = W2[(k0 + 2 * p + 1) * NCLS + n];
            ws2[p][n] = __floats2half2_rn(w0, w1);
        }
        __syncthreads();

#pragma unroll
        for (int ks = 0; ks < 2; ks++) {
            int kA = ks * 8 + qcol;
            int mr = wid * 16 + qrow;
            unsigned a[4];
            a[0] = *(unsigned*)&hs2[kA][mr];
            a[1] = *(unsigned*)&hs2[kA][mr + 8];
            a[2] = *(unsigned*)&hs2[kA + 4][mr];
            a[3] = *(unsigned*)&hs2[kA + 4][mr + 8];
#pragma unroll
            for (int u = 0; u < 5; u++) {
                unsigned b[2];
                b[0] = *(unsigned*)&ws2[kA][u * 8 + qrow];
                b[1] = *(unsigned*)&ws2[kA + 4][u * 8 + qrow];
                MMA_F16(d[u], a, b);
            }
        }
        __syncthreads();
    }

    {
        int mr = wid * 16 + qrow;
#pragma unroll
        for (int u = 0; u < 5; u++) {
            int c = u * 8 + qcol * 2;
            float2 bb = *(const float2*)&b2[c];
            lg[mr][c]         = d[u][0] + bb.x;
            lg[mr][c + 1]     = d[u][1] + bb.y;
            lg[mr + 8][c]     = d[u][2] + bb.x;
            lg[mr + 8][c + 1] = d[u][3] + bb.y;
        }
    }
    __syncthreads();

    if (tid < 128) {
        int row = m0 + tid;
        if (row < N_NODES) {
            float m = -1e30f;
#pragma unroll
            for (int c = 0; c < NCLS; c++) m = fmaxf(m, lg[tid][c]);
            float s = 0.f;
#pragma unroll
            for (int c = 0; c < NCLS; c++) s += expf(lg[tid][c] - m);
            float sub = m + logf(s);
            float* orow = &out[row * NCLS];
#pragma unroll
            for (int c = 0; c < NCLS; c++) orow[c] = lg[tid][c] - sub;
        }
    }
}

// ---------------- launch ----------------
extern "C" void kernel_launch(void* const* d_in, const int* in_sizes, int n_in,
                              void* d_out, int out_size) {
    const float* features = (const float*)d_in[0];
    const int*   src      = (const int*)d_in[1];
    const int*   dst      = (const int*)d_in[2];
    const float* W1       = (const float*)d_in[3];
    const float* b1       = (const float*)d_in[4];
    const float* W2       = (const float*)d_in[5];
    const float* b2       = (const float*)d_in[6];
    float*       out      = (float*)d_out;

    const int NB  = (N_NODES + 255) / 256;      // 196
    const int E4B = (N_EDGES / 4 + 255) / 256;  // 782
    const int PB  = (N_NODES + 7) / 8;          // 6250
    const float4* feat4 = (const float4*)features;

    zero_deg_kernel<<<NB, 256>>>();
    deg_kernel<<<E4B, 256>>>((const int4*)dst);
    scan1_kernel<<<SCAN_BLOCKS, 256>>>();
    scan3_kernel<<<4 * SCAN_BLOCKS, 256>>>(feat4);
    fill_kernel<<<E4B, 256>>>((const int4*)src, (const int4*)dst);

    prop_kernel<0><<<PB, 256>>>(0);   // x0 -> x1, y = x0 + x1
    prop_kernel<1><<<PB, 256>>>(1);   // x1 -> x0, y += x2
    prop_kernel<2><<<PB, 256>>>(0);   // x0(x2) -> final y/4 into g_xh1

    dim3 g1((N_NODES + 127) / 128, HID / 128);  // (391, 1)... (391, 2)? HID/128=2
    gemm1_kernel<<<g1, 256>>>(W1, b1);

    const int G2B = (N_NODES + 127) / 128;      // 391
    gemm2_kernel<<<G2B, 256>>>(W2, b2, out);
}

// round 14
// speedup vs baseline: 2.2630x; 1.0355x over previous
#include <cuda_runtime.h>
#include <cuda_fp16.h>
#include <math.h>

#define N_NODES 50000
#define N_EDGES 800000
#define F_DIM   128
#define F4      32      // float4 per feature row
#define HID     256
#define NCLS    40

#define SCAN_BLOCKS ((N_NODES + 255) / 256)   // 196

// ---------------- device scratch (static: no allocation allowed) ----------------
// RULE (learned R3-R5): never pass __device__ symbol addresses from host code —
// on GB300 the host-side shadow resolves via ATS to HOST memory. All buffer
// selection happens inside device code.
__device__ int      g_deg[N_NODES];
__device__ int      g_rowstart[N_NODES + 1];
__device__ int      g_cursor[N_NODES];
__device__ int      g_bsum[SCAN_BLOCKS];
__device__ float    g_norm[N_NODES];
__device__ unsigned g_csr[N_EDGES];          // (src << 16) | fp16(norm[src]) bits
__device__ __half   g_xh0[N_NODES * F_DIM];  // fp16 ping
__device__ __half   g_xh1[N_NODES * F_DIM];  // fp16 pong; holds final fp16 y
__device__ __half   g_yh [N_NODES * F_DIM];  // fp16 running sum (fp32 math)
__device__ __half   g_h  [N_NODES * HID];    // fp16 hidden activations

// ---------------- build: degree ----------------
__global__ void zero_deg_kernel() {
    int i = blockIdx.x * blockDim.x + threadIdx.x;
    if (i < N_NODES) g_deg[i] = 0;
}

__global__ void deg_kernel(const int4* __restrict__ dst4) {
    int i = blockIdx.x * blockDim.x + threadIdx.x;
    if (i < N_EDGES / 4) {
        int4 d = dst4[i];
        atomicAdd(&g_deg[d.x], 1);
        atomicAdd(&g_deg[d.y], 1);
        atomicAdd(&g_deg[d.z], 1);
        atomicAdd(&g_deg[d.w], 1);
    }
}

// ---------------- hierarchical scan ----------------
__device__ __forceinline__ int warp_incl_scan(int v, int lane) {
#pragma unroll
    for (int o = 1; o < 32; o <<= 1) {
        int n = __shfl_up_sync(0xffffffffu, v, o);
        if (lane >= o) v += n;
    }
    return v;
}

__device__ __forceinline__ int block_incl_scan_256(int v, int tid) {
    __shared__ int ws[8];
    int lane = tid & 31, w = tid >> 5;
    int incl = warp_incl_scan(v, lane);
    if (lane == 31) ws[w] = incl;
    __syncthreads();
    if (w == 0) {
        int s = (lane < 8) ? ws[lane] : 0;
        s = warp_incl_scan(s, lane);
        if (lane < 8) ws[lane] = s;
    }
    __syncthreads();
    if (w > 0) incl += ws[w - 1];
    return incl;
}

__global__ void scan1_kernel() {
    int tid = threadIdx.x;
    int i = blockIdx.x * 256 + tid;
    int v = (i < N_NODES) ? g_deg[i] : 0;
    if (i < N_NODES) g_norm[i] = rsqrtf((float)(v < 1 ? 1 : v));
    int incl = block_incl_scan_256(v, tid);
    if (i < N_NODES) g_rowstart[i] = incl - v;
    if (tid == 255) g_bsum[blockIdx.x] = incl;
}

// phase 2: blocks < SCAN_BLOCKS do offset fixup; ALL blocks convert the
// feature matrix to fp16 via grid-stride (higher copy occupancy)
__global__ void scan3_kernel(const float4* __restrict__ feat) {
    __shared__ int ssum[8];
    int tid = threadIdx.x;
    int bid = blockIdx.x;
    int lane = tid & 31, w = tid >> 5;

    if (bid < SCAN_BLOCKS) {
        int v = (tid < bid && tid < SCAN_BLOCKS) ? g_bsum[tid] : 0;
#pragma unroll
        for (int o = 16; o > 0; o >>= 1) v += __shfl_down_sync(0xffffffffu, v, o);
        if (lane == 0) ssum[w] = v;
        __syncthreads();
        if (tid == 0) {
            int s = 0;
#pragma unroll
            for (int i = 0; i < 8; i++) s += ssum[i];
            ssum[0] = s;
        }
        __syncthreads();
        int off = ssum[0];

        int i = bid * 256 + tid;
        if (i < N_NODES) {
            int r = g_rowstart[i] + off;
            g_rowstart[i] = r;
            g_cursor[i]   = r;
        }
        if (i == 0) g_rowstart[N_NODES] = N_EDGES;
    }

    // grid-stride fp16 conversion of features (all blocks)
    uint2* xh0v = (uint2*)g_xh0;
    int stride = gridDim.x * 256;
    for (int j = bid * 256 + tid; j < N_NODES * F4; j += stride) {
        float4 f = feat[j];
        __half2 h0 = __floats2half2_rn(f.x, f.y);
        __half2 h1 = __floats2half2_rn(f.z, f.w);
        uint2 u;
        u.x = *(unsigned*)&h0;
        u.y = *(unsigned*)&h1;
        xh0v[j] = u;
    }
}

// fill CSR: packed (src<<16)|fp16(norm[src]), int4 edge loads
__device__ __forceinline__ unsigned pack_edge(int s) {
    __half hw = __float2half_rn(g_norm[s]);
    return ((unsigned)s << 16) | (unsigned)__half_as_ushort(hw);
}

__global__ void fill_kernel(const int4* __restrict__ src4, const int4* __restrict__ dst4) {
    int i = blockIdx.x * blockDim.x + threadIdx.x;
    if (i < N_EDGES / 4) {
        int4 s = src4[i];
        int4 d = dst4[i];
        int pos;
        pos = atomicAdd(&g_cursor[d.x], 1); g_csr[pos] = pack_edge(s.x);
        pos = atomicAdd(&g_cursor[d.y], 1); g_csr[pos] = pack_edge(s.y);
        pos = atomicAdd(&g_cursor[d.z], 1); g_csr[pos] = pack_edge(s.z);
        pos = atomicAdd(&g_cursor[d.w], 1); g_csr[pos] = pack_edge(s.w);
    }
}

// ---------------- propagation: pull over fp16 CSR gather, fp32 accumulate -------
// warp per node; lane owns 4 feature dims (8B fp16); 8-deep gather pipeline
// MODE 0: y16 = xin16[node] + acc ; MODE 1: y16 += acc ;
// MODE 2: y_final = (y16 + acc)*0.25 -> fp16 into xout (g_xh1)
__device__ __forceinline__ void gacc(uint2 u, float w, float4& acc) {
    float2 f0 = __half22float2(*(__half2*)&u.x);
    float2 f1 = __half22float2(*(__half2*)&u.y);
    acc.x = fmaf(f0.x, w, acc.x);
    acc.y = fmaf(f0.y, w, acc.y);
    acc.z = fmaf(f1.x, w, acc.z);
    acc.w = fmaf(f1.y, w, acc.w);
}

__device__ __forceinline__ uint2 pack_h4(float4 v) {
    __half2 o0 = __floats2half2_rn(v.x, v.y);
    __half2 o1 = __floats2half2_rn(v.z, v.w);
    uint2 u;
    u.x = *(unsigned*)&o0;
    u.y = *(unsigned*)&o1;
    return u;
}

__device__ __forceinline__ float4 unpack_h4(uint2 u) {
    float2 f0 = __half22float2(*(__half2*)&u.x);
    float2 f1 = __half22float2(*(__half2*)&u.y);
    return make_float4(f0.x, f0.y, f1.x, f1.y);
}

__device__ __forceinline__ float wt_of(unsigned c) {
    return __half2float(__ushort_as_half((unsigned short)(c & 0xffffu)));
}

template<int MODE>
__global__ void prop_kernel(int dir) {
    const __half* __restrict__ xin  = dir ? g_xh1 : g_xh0;
    __half*       __restrict__ xout = dir ? g_xh0 : g_xh1;

    int node = blockIdx.x * 8 + (threadIdx.x >> 5);
    int lane = threadIdx.x & 31;
    if (node >= N_NODES) return;

    int beg = g_rowstart[node];
    int end = g_rowstart[node + 1];
    int lane4 = lane * 4;

    float4 acc = make_float4(0.f, 0.f, 0.f, 0.f);
    int e = beg;
    for (; e + 8 <= end; e += 8) {
        unsigned c0 = __ldg(&g_csr[e + 0]);
        unsigned c1 = __ldg(&g_csr[e + 1]);
        unsigned c2 = __ldg(&g_csr[e + 2]);
        unsigned c3 = __ldg(&g_csr[e + 3]);
        unsigned c4 = __ldg(&g_csr[e + 4]);
        unsigned c5 = __ldg(&g_csr[e + 5]);
        unsigned c6 = __ldg(&g_csr[e + 6]);
        unsigned c7 = __ldg(&g_csr[e + 7]);
        uint2 u0 = __ldg((const uint2*)(xin + (c0 >> 16) * F_DIM + lane4));
        uint2 u1 = __ldg((const uint2*)(xin + (c1 >> 16) * F_DIM + lane4));
        uint2 u2 = __ldg((const uint2*)(xin + (c2 >> 16) * F_DIM + lane4));
        uint2 u3 = __ldg((const uint2*)(xin + (c3 >> 16) * F_DIM + lane4));
        uint2 u4 = __ldg((const uint2*)(xin + (c4 >> 16) * F_DIM + lane4));
        uint2 u5 = __ldg((const uint2*)(xin + (c5 >> 16) * F_DIM + lane4));
        uint2 u6 = __ldg((const uint2*)(xin + (c6 >> 16) * F_DIM + lane4));
        uint2 u7 = __ldg((const uint2*)(xin + (c7 >> 16) * F_DIM + lane4));
        gacc(u0, wt_of(c0), acc);
        gacc(u1, wt_of(c1), acc);
        gacc(u2, wt_of(c2), acc);
        gacc(u3, wt_of(c3), acc);
        gacc(u4, wt_of(c4), acc);
        gacc(u5, wt_of(c5), acc);
        gacc(u6, wt_of(c6), acc);
        gacc(u7, wt_of(c7), acc);
    }
    for (; e + 2 <= end; e += 2) {
        unsigned c0 = __ldg(&g_csr[e + 0]);
        unsigned c1 = __ldg(&g_csr[e + 1]);
        uint2 u0 = __ldg((const uint2*)(xin + (c0 >> 16) * F_DIM + lane4));
        uint2 u1 = __ldg((const uint2*)(xin + (c1 >> 16) * F_DIM + lane4));
        gacc(u0, wt_of(c0), acc);
        gacc(u1, wt_of(c1), acc);
    }
    for (; e < end; e++) {
        unsigned c = __ldg(&g_csr[e]);
        uint2 u = __ldg((const uint2*)(xin + (c >> 16) * F_DIM + lane4));
        gacc(u, wt_of(c), acc);
    }

    float nd = g_norm[node];
    acc.x *= nd; acc.y *= nd; acc.z *= nd; acc.w *= nd;

    int hoff = node * F_DIM + lane4;
    if (MODE == 0) {
        *(uint2*)(xout + hoff) = pack_h4(acc);
        float4 f = unpack_h4(__ldg((const uint2*)(xin + hoff)));
        f.x += acc.x; f.y += acc.y; f.z += acc.z; f.w += acc.w;
        *(uint2*)(g_yh + hoff) = pack_h4(f);
    } else if (MODE == 1) {
        *(uint2*)(xout + hoff) = pack_h4(acc);
        float4 yv = unpack_h4(*(const uint2*)(g_yh + hoff));
        yv.x += acc.x; yv.y += acc.y; yv.z += acc.z; yv.w += acc.w;
        *(uint2*)(g_yh + hoff) = pack_h4(yv);
    } else {
        float4 yv = unpack_h4(*(const uint2*)(g_yh + hoff));
        yv.x = (yv.x + acc.x) * 0.25f;
        yv.y = (yv.y + acc.y) * 0.25f;
        yv.z = (yv.z + acc.z) * 0.25f;
        yv.w = (yv.w + acc.w) * 0.25f;
        *(uint2*)(xout + hoff) = pack_h4(yv);   // final pre-scaled y -> g_xh1
    }
}

// ---------------- fp16 MMA helper -----------------------------------------------
#define MMA_F16(D, A, B) \
    asm volatile("mma.sync.aligned.m16n8k16.row.col.f32.f16.f16.f32 " \
        "{%0,%1,%2,%3}, {%4,%5,%6,%7}, {%8,%9}, {%0,%1,%2,%3};" \
        : "+f"((D)[0]), "+f"((D)[1]), "+f"((D)[2]), "+f"((D)[3]) \
        : "r"((A)[0]), "r"((A)[1]), "r"((A)[2]), "r"((A)[3]), \
          "r"((B)[0]), "r"((B)[1]))

// ---------------- GEMM1 (fp16 MMA): h = relu( y16 @ W1 + b1 ) -------------------
// BM=128, BN=128, BK=16, 256 threads = 8 warps (2m x 4n), warp tile 64x32
__global__ __launch_bounds__(256) void gemm1_kernel(const float* __restrict__ W1,
                                                    const float* __restrict__ b1) {
    __shared__ __half2 As2[8][132];   // [k2][m]
    __shared__ __half2 Bs2[8][132];   // [k2][n]

    int tid  = threadIdx.x;
    int lane = tid & 31;
    int wid  = tid >> 5;
    int warp_m = wid & 1;
    int warp_n = wid >> 1;
    int qrow = lane >> 2;
    int qcol = lane & 3;

    int m0 = blockIdx.x * 128;
    int n0 = blockIdx.y * 128;

    int arow = tid >> 1;             // 0..127
    int ak   = (tid & 1) * 8;        // halves 0 or 8

    float d[4][4][4];
#pragma unroll
    for (int t = 0; t < 4; t++)
#pragma unroll
        for (int u = 0; u < 4; u++)
#pragma unroll
            for (int i = 0; i < 4; i++) d[t][u][i] = 0.f;

    for (int k0 = 0; k0 < F_DIM; k0 += 16) {
        {
            int gm = m0 + arow;
            uint4 u = make_uint4(0u, 0u, 0u, 0u);
            if (gm < N_NODES) u = *(const uint4*)(g_xh1 + gm * F_DIM + k0 + ak);
            int p = ak >> 1;
            As2[p + 0][arow] = *(__half2*)&u.x;
            As2[p + 1][arow] = *(__half2*)&u.y;
            As2[p + 2][arow] = *(__half2*)&u.z;
            As2[p + 3][arow] = *(__half2*)&u.w;
        }
#pragma unroll
        for (int q = 0; q < 4; q++) {
            int idx = tid + 256 * q;
            int p = idx >> 7;
            int n = idx & 127;
            float w0 = W1[(k0 + 2 * p)     * HID + n0 + n];
            float w1 = W1[(k0 + 2 * p + 1) * HID + n0 + n];
            Bs2[p][n] = __floats2half2_rn(w0, w1);
        }
        __syncthreads();

        {
            unsigned a[4][4], b[4][2];
#pragma unroll
            for (int t = 0; t < 4; t++) {
                int mr = warp_m * 64 + t * 16 + qrow;
                a[t][0] = *(unsigned*)&As2[qcol][mr];
                a[t][1] = *(unsigned*)&As2[qcol][mr + 8];
                a[t][2] = *(unsigned*)&As2[qcol + 4][mr];
                a[t][3] = *(unsigned*)&As2[qcol + 4][mr + 8];
            }
#pragma unroll
            for (int u = 0; u < 4; u++) {
                int bcol = warp_n * 32 + u * 8 + qrow;
                b[u][0] = *(unsigned*)&Bs2[qcol][bcol];
                b[u][1] = *(unsigned*)&Bs2[qcol + 4][bcol];
            }
#pragma unroll
            for (int t = 0; t < 4; t++)
#pragma unroll
                for (int u = 0; u < 4; u++)
                    MMA_F16(d[t][u], a[t], b[u]);
        }
        __syncthreads();
    }

#pragma unroll
    for (int t = 0; t < 4; t++) {
        int r0 = m0 + warp_m * 64 + t * 16 + qrow;
#pragma unroll
        for (int u = 0; u < 4; u++) {
            int c = n0 + warp_n * 32 + u * 8 + qcol * 2;
            float2 bb = *(const float2*)&b1[c];
            if (r0 < N_NODES) {
                __half2 o = __floats2half2_rn(fmaxf(d[t][u][0] + bb.x, 0.f),
                                              fmaxf(d[t][u][1] + bb.y, 0.f));
                *(__half2*)(g_h + r0 * HID + c) = o;
            }
            if (r0 + 8 < N_NODES) {
                __half2 o = __floats2half2_rn(fmaxf(d[t][u][2] + bb.x, 0.f),
                                              fmaxf(d[t][u][3] + bb.y, 0.f));
                *(__half2*)(g_h + (r0 + 8) * HID + c) = o;
            }
        }
    }
}

// ---------------- GEMM2 (fp16 MMA) + fused log_softmax --------------------------
__global__ __launch_bounds__(256) void gemm2_kernel(const float* __restrict__ W2,
                                                    const float* __restrict__ b2,
                                                    float* __restrict__ out) {
    __shared__ __half2 hs2[16][132];
    __shared__ __half2 ws2[16][44];
    __shared__ float   lg[128][41];

    int tid  = threadIdx.x;
    int lane = tid & 31;
    int wid  = tid >> 5;
    int qrow = lane >> 2;
    int qcol = lane & 3;
    int m0 = blockIdx.x * 128;

    float d[5][4];
#pragma unroll
    for (int u = 0; u < 5; u++)
#pragma unroll
        for (int i = 0; i < 4; i++) d[u][i] = 0.f;

    int arow = tid >> 1;
    int ak   = (tid & 1) * 16;

    for (int k0 = 0; k0 < HID; k0 += 32) {
        {
            int gm = m0 + arow;
            const __half* hp = g_h + gm * HID + k0 + ak;
            uint4 v0 = make_uint4(0u, 0u, 0u, 0u), v1 = v0;
            if (gm < N_NODES) {
                v0 = *(const uint4*)hp;
                v1 = *(const uint4*)(hp + 8);
            }
            int k2b = ak >> 1;
            hs2[k2b + 0][arow] = *(__half2*)&v0.x;
            hs2[k2b + 1][arow] = *(__half2*)&v0.y;
            hs2[k2b + 2][arow] = *(__half2*)&v0.z;
            hs2[k2b + 3][arow] = *(__half2*)&v0.w;
            hs2[k2b + 4][arow] = *(__half2*)&v1.x;
            hs2[k2b + 5][arow] = *(__half2*)&v1.y;
            hs2[k2b + 6][arow] = *(__half2*)&v1.z;
            hs2[k2b + 7][arow] = *(__half2*)&v1.w;
        }
        for (int idx = tid; idx < 16 * NCLS; idx += 256) {
            int p = idx / NCLS, n = idx - p * NCLS;
            float w0 = W2[(k0 + 2 * p)     * NCLS + n];
            float w1 = W2[(k0 + 2 * p + 1) * NCLS + n];
            ws2[p][n] = __floats2half2_rn(w0, w1);
        }
        __syncthreads();

#pragma unroll
        for (int ks = 0; ks < 2; ks++) {
            int kA = ks * 8 + qcol;
            int mr = wid * 16 + qrow;
            unsigned a[4];
            a[0] = *(unsigned*)&hs2[kA][mr];
            a[1] = *(unsigned*)&hs2[kA][mr + 8];
            a[2] = *(unsigned*)&hs2[kA + 4][mr];
            a[3] = *(unsigned*)&hs2[kA + 4][mr + 8];
#pragma unroll
            for (int u = 0; u < 5; u++) {
                unsigned b[2];
                b[0] = *(unsigned*)&ws2[kA][u * 8 + qrow];
                b[1] = *(unsigned*)&ws2[kA + 4][u * 8 + qrow];
                MMA_F16(d[u], a, b);
            }
        }
        __syncthreads();
    }

    {
        int mr = wid * 16 + qrow;
#pragma unroll
        for (int u = 0; u < 5; u++) {
            int c = u * 8 + qcol * 2;
            float2 bb = *(const float2*)&b2[c];
            lg[mr][c]         = d[u][0] + bb.x;
            lg[mr][c + 1]     = d[u][1] + bb.y;
            lg[mr + 8][c]     = d[u][2] + bb.x;
            lg[mr + 8][c + 1] = d[u][3] + bb.y;
        }
    }
    __syncthreads();

    if (tid < 128) {
        int row = m0 + tid;
        if (row < N_NODES) {
            float m = -1e30f;
#pragma unroll
            for (int c = 0; c < NCLS; c++) m = fmaxf(m, lg[tid][c]);
            float s = 0.f;
#pragma unroll
            for (int c = 0; c < NCLS; c++) s += expf(lg[tid][c] - m);
            float sub = m + logf(s);
            float* orow = &out[row * NCLS];
#pragma unroll
            for (int c = 0; c < NCLS; c++) orow[c] = lg[tid][c] - sub;
        }
    }
}

// ---------------- launch ----------------
extern "C" void kernel_launch(void* const* d_in, const int* in_sizes, int n_in,
                              void* d_out, int out_size) {
    const float* features = (const float*)d_in[0];
    const int*   src      = (const int*)d_in[1];
    const int*   dst      = (const int*)d_in[2];
    const float* W1       = (const float*)d_in[3];
    const float* b1       = (const float*)d_in[4];
    const float* W2       = (const float*)d_in[5];
    const float* b2       = (const float*)d_in[6];
    float*       out      = (float*)d_out;

    const int NB  = (N_NODES + 255) / 256;      // 196
    const int E4B = (N_EDGES / 4 + 255) / 256;  // 782
    const int PB  = (N_NODES + 7) / 8;          // 6250
    const float4* feat4 = (const float4*)features;

    zero_deg_kernel<<<NB, 256>>>();
    deg_kernel<<<E4B, 256>>>((const int4*)dst);
    scan1_kernel<<<SCAN_BLOCKS, 256>>>();
    scan3_kernel<<<6 * SCAN_BLOCKS, 256>>>(feat4);
    fill_kernel<<<E4B, 256>>>((const int4*)src, (const int4*)dst);

    prop_kernel<0><<<PB, 256>>>(0);   // x0 -> x1, y = x0 + x1
    prop_kernel<1><<<PB, 256>>>(1);   // x1 -> x0, y += x2
    prop_kernel<2><<<PB, 256>>>(0);   // x0(x2) -> final y/4 into g_xh1

    dim3 g1((N_NODES + 127) / 128, HID / 128);  // (391, 2)
    gemm1_kernel<<<g1, 256>>>(W1, b1);

    const int G2B = (N_NODES + 127) / 128;      // 391
    gemm2_kernel<<<G2B, 256>>>(W2, b2, out);
}